// round 12
// baseline (speedup 1.0000x reference)
#include <cuda_runtime.h>
#include <cuda_fp16.h>

#define NN    100000
#define FEAT  128
#define CLS   40
#define EMAX  1600000

// ---- scratch (static device globals; no allocation allowed) ----
__device__ int    g_degi[NN];                // zero at load; re-zeroed by spmm128
__device__ float  g_dinv[NN];
__device__ __half g_Hh[(size_t)NN * FEAT];   // pre-scaled fp16 messages h*dinv
__device__ __half g_AGG[(size_t)NN * FEAT];  // fp16 relu'd conv output
__device__ __half g_H2h[(size_t)NN * CLS];   // layer-2 pre-scaled fp16 messages
__device__ __half g_W0h[16384];
__device__ __half g_W1h[16384];
__device__ __half g_W2p[128 * 64];           // W2 padded 40->64 cols
__device__ int    g_rowptr[NN];              // segment start (unordered)
__device__ int    g_cursor[NN];              // post-fill: segment end
__device__ int    g_csr[EMAX];
__device__ int    g_total;

// ---- helpers ----
__device__ __forceinline__ unsigned sm_u32(const void* p) {
    return (unsigned)__cvta_generic_to_shared(p);
}
__device__ __forceinline__ void ldm_x4(unsigned* r, unsigned a) {
    asm volatile("ldmatrix.sync.aligned.m8n8.x4.shared.b16 {%0,%1,%2,%3}, [%4];"
                 : "=r"(r[0]), "=r"(r[1]), "=r"(r[2]), "=r"(r[3]) : "r"(a));
}
__device__ __forceinline__ void ldm_x4t(unsigned* r, unsigned a) {
    asm volatile("ldmatrix.sync.aligned.m8n8.x4.trans.shared.b16 {%0,%1,%2,%3}, [%4];"
                 : "=r"(r[0]), "=r"(r[1]), "=r"(r[2]), "=r"(r[3]) : "r"(a));
}
__device__ __forceinline__ void mma16816(float* d, const unsigned* a,
                                         const unsigned* b) {
    asm volatile(
        "mma.sync.aligned.m16n8k16.row.col.f32.f16.f16.f32 "
        "{%0,%1,%2,%3},{%4,%5,%6,%7},{%8,%9},{%0,%1,%2,%3};"
        : "+f"(d[0]), "+f"(d[1]), "+f"(d[2]), "+f"(d[3])
        : "r"(a[0]), "r"(a[1]), "r"(a[2]), "r"(a[3]), "r"(b[0]), "r"(b[1]));
}
__device__ __forceinline__ void cp16(unsigned d, const void* s) {
    asm volatile("cp.async.ca.shared.global [%0], [%1], 16;" :: "r"(d), "l"(s));
}
__device__ __forceinline__ void cp16p(unsigned d, const void* s, bool p) {
    int sz = p ? 16 : 0;
    asm volatile("cp.async.ca.shared.global [%0], [%1], 16, %2;"
                 :: "r"(d), "l"(s), "r"(sz));
}
__device__ __forceinline__ void cp_wait() {
    asm volatile("cp.async.commit_group;" ::: "memory");
    asm volatile("cp.async.wait_group 0;" ::: "memory");
}
__device__ __forceinline__ bool ei_is64(const void* ei, int n) {
    const unsigned long long* p = (const unsigned long long*)ei;
    return p[0] < (unsigned long long)n && p[1] < (unsigned long long)n;
}

// ------------------------------------------------------------------
// CSR build (unordered segments): count -> offset -> fill
// ------------------------------------------------------------------
__global__ void k_count(const void* ei, int n, int E) {
    if (blockIdx.x == 0 && threadIdx.x == 0) g_total = 0;
    int e = blockIdx.x * blockDim.x + threadIdx.x;
    if (e >= E) return;
    bool is64 = ei_is64(ei, n);
    int dst = is64 ? (int)((const long long*)ei)[E + e]
                   : ((const int*)ei)[E + e];
    atomicAdd(&g_degi[dst], 1);
}

// per-256-node block: local scan + atomic base; also writes dinv
__global__ void k_offset(int n) {
    __shared__ int wsum[8];
    __shared__ int base;
    int t = threadIdx.x;
    int i = blockIdx.x * 256 + t;
    int lane = t & 31, warp = t >> 5;
    int deg = (i < n) ? g_degi[i] : 0;
    if (i < n) g_dinv[i] = rsqrtf((float)deg + 1.f);
    int v = deg;
#pragma unroll
    for (int off = 1; off < 32; off <<= 1) {
        int x = __shfl_up_sync(0xffffffffu, v, off);
        if (lane >= off) v += x;
    }
    if (lane == 31) wsum[warp] = v;
    __syncthreads();
    if (warp == 0 && lane < 8) {
        int s = wsum[lane];
#pragma unroll
        for (int off = 1; off < 8; off <<= 1) {
            int x = __shfl_up_sync(0xffu, s, off);
            if (lane >= off) s += x;
        }
        wsum[lane] = s;
    }
    __syncthreads();
    if (t == 0) base = atomicAdd(&g_total, wsum[7]);
    __syncthreads();
    if (i < n) {
        int incl = v + (warp > 0 ? wsum[warp - 1] : 0);
        int r = base + incl - deg;
        g_rowptr[i] = r;
        g_cursor[i] = r;
    }
}

__global__ void k_fill(const void* ei, int n, int E) {
    int e = blockIdx.x * blockDim.x + threadIdx.x;
    if (e >= E) return;
    bool is64 = ei_is64(ei, n);
    int s, d;
    if (is64) {
        const long long* p = (const long long*)ei;
        s = (int)p[e]; d = (int)p[E + e];
    } else {
        const int* p = (const int*)ei;
        s = p[e]; d = p[E + e];
    }
    int pos = atomicAdd(&g_cursor[d], 1);
    g_csr[pos] = s;
}

// weights -> fp16 (W2 padded 40->64)
__global__ void k_convW(const float* W0, const float* W1, const float* W2) {
    int i = blockIdx.x * blockDim.x + threadIdx.x;
    if (i < 16384) {
        g_W0h[i] = __float2half_rn(W0[i]);
    } else if (i < 32768) {
        g_W1h[i - 16384] = __float2half_rn(W1[i - 16384]);
    } else if (i < 32768 + 128 * 64) {
        int j = i - 32768;
        int k = j >> 6, c = j & 63;
        g_W2p[j] = __float2half_rn(c < 40 ? W2[k * 40 + c] : 0.f);
    }
}

// ------------------------------------------------------------------
// Tensor-core GEMM (K=128, Nout=128), single-shot smem, fp16 W:
//   h  = A @ Wh ; Hh = half(h * dinv)
// ------------------------------------------------------------------
#define SPITCH 136
#define AS(r, c) dsm[(r) * SPITCH + (c)]
#define WS(r, c) dsm[17408 + (r) * SPITCH + (c)]
#define HS(r, c) dsm[(r) * SPITCH + (c)]

template <bool HIN>
__global__ __launch_bounds__(256)
void k_gemm128h(const void* __restrict__ A, const __half* __restrict__ Wh,
                __half* __restrict__ Hh, int n) {
    extern __shared__ __half dsm[];
    const int tid  = threadIdx.x;
    const int lane = tid & 31;
    const int warp = tid >> 5;
    const int wm   = warp & 3;
    const int wn   = warp >> 2;
    const int row0 = blockIdx.x * 128;

    float acc[2][8][4];
#pragma unroll
    for (int mi = 0; mi < 2; mi++)
#pragma unroll
        for (int ni = 0; ni < 8; ni++)
#pragma unroll
            for (int q = 0; q < 4; q++) acc[mi][ni][q] = 0.f;

    const int ar = tid >> 1, ac = (tid & 1) * 64;
    {
        const __half* Wrow = Wh + ar * 128 + ac;
#pragma unroll
        for (int u = 0; u < 8; u++)
            cp16(sm_u32(&WS(ar, ac + u * 8)), Wrow + u * 8);
    }
    if (HIN) {
        int gr = row0 + ar;
        bool ok = gr < n;
        const __half* Arow = (const __half*)A + (size_t)gr * 128 + ac;
#pragma unroll
        for (int u = 0; u < 8; u++)
            cp16p(sm_u32(&AS(ar, ac + u * 8)), Arow + u * 8, ok);
    } else {
        int gr = row0 + ar;
        const float* Arow = (const float*)A + (size_t)gr * 128 + ac;
#pragma unroll
        for (int u = 0; u < 8; u++) {
            float4 f0 = make_float4(0.f, 0.f, 0.f, 0.f), f1 = f0;
            if (gr < n) {
                f0 = *(const float4*)(Arow + u * 8);
                f1 = *(const float4*)(Arow + u * 8 + 4);
            }
            __half2 hh[4];
            hh[0] = __floats2half2_rn(f0.x, f0.y);
            hh[1] = __floats2half2_rn(f0.z, f0.w);
            hh[2] = __floats2half2_rn(f1.x, f1.y);
            hh[3] = __floats2half2_rn(f1.z, f1.w);
            *(uint4*)&AS(ar, ac + u * 8) = *(uint4*)hh;
        }
    }
    cp_wait();
    __syncthreads();

#pragma unroll
    for (int kk = 0; kk < 8; kk++) {
        unsigned af[2][4];
#pragma unroll
        for (int mi = 0; mi < 2; mi++) {
            int r = wm * 32 + mi * 16 + (lane & 15);
            int kh = kk * 16 + (lane >> 4) * 8;
            ldm_x4(af[mi], sm_u32(&AS(r, kh)));
        }
        unsigned bf[8][2];
#pragma unroll
        for (int nt = 0; nt < 4; nt++) {
            int g = lane >> 3, r = lane & 7;
            int krow = kk * 16 + (g & 1) * 8 + r;
            int ncol = wn * 64 + nt * 16 + (g >> 1) * 8;
            unsigned t[4];
            ldm_x4t(t, sm_u32(&WS(krow, ncol)));
            bf[nt * 2 + 0][0] = t[0]; bf[nt * 2 + 0][1] = t[1];
            bf[nt * 2 + 1][0] = t[2]; bf[nt * 2 + 1][1] = t[3];
        }
#pragma unroll
        for (int mi = 0; mi < 2; mi++)
#pragma unroll
            for (int ni = 0; ni < 8; ni++)
                mma16816(acc[mi][ni], af[mi], bf[ni]);
    }

    __syncthreads();
    {
        const int r1 = lane >> 2;
        const int c2 = (lane & 3) * 2;
#pragma unroll
        for (int mi = 0; mi < 2; mi++) {
            int r = wm * 32 + mi * 16 + r1;
#pragma unroll
            for (int ni = 0; ni < 8; ni++) {
                int col = wn * 64 + ni * 8 + c2;
                __half2 h01 = __floats2half2_rn(acc[mi][ni][0], acc[mi][ni][1]);
                __half2 h23 = __floats2half2_rn(acc[mi][ni][2], acc[mi][ni][3]);
                *(__half2*)&HS(r, col)     = h01;
                *(__half2*)&HS(r + 8, col) = h23;
            }
        }
    }
    __syncthreads();
    {
        int rrow  = tid >> 4;
        int chunk = tid & 15;
#pragma unroll
        for (int p = 0; p < 8; p++) {
            int r = p * 16 + rrow;
            int gr = row0 + r;
            if (gr < n) {
                __half2 d2 = __float2half2_rn(g_dinv[gr]);
                uint4 u = *(uint4*)&HS(r, chunk * 8);
                __half2* hp = (__half2*)&u;
                hp[0] = __hmul2(hp[0], d2); hp[1] = __hmul2(hp[1], d2);
                hp[2] = __hmul2(hp[2], d2); hp[3] = __hmul2(hp[3], d2);
                *(uint4*)(Hh + (size_t)gr * 128 + chunk * 8) = u;
            }
        }
    }
}

// ------------------------------------------------------------------
// Tensor-core GEMM (K=128, Nout=64 padded; 40 real), fp16 A + W:
//   h2 = A @ W2p ; H2h = half(h2 * dinv)
// ------------------------------------------------------------------
#define WS40(r, c) dsm[17408 + (r) * 72 + (c)]

__global__ __launch_bounds__(256)
void k_gemm40h(const __half* __restrict__ A, __half* __restrict__ H2h, int n) {
    extern __shared__ __half dsm[];
    const int tid  = threadIdx.x;
    const int lane = tid & 31;
    const int warp = tid >> 5;
    const int wm   = warp & 3;
    const int wn   = warp >> 2;
    const int row0 = blockIdx.x * 128;

    float acc[2][4][4];
#pragma unroll
    for (int mi = 0; mi < 2; mi++)
#pragma unroll
        for (int ni = 0; ni < 4; ni++)
#pragma unroll
            for (int q = 0; q < 4; q++) acc[mi][ni][q] = 0.f;

    const int ar = tid >> 1, ac = (tid & 1) * 64;
    {
        int gr = row0 + ar;
        bool ok = gr < n;
        const __half* Arow = A + (size_t)gr * 128 + ac;
#pragma unroll
        for (int u = 0; u < 8; u++)
            cp16p(sm_u32(&AS(ar, ac + u * 8)), Arow + u * 8, ok);
    }
    {
        const int wr = tid >> 1, wc = (tid & 1) * 32;
        const __half* Wrow = g_W2p + wr * 64 + wc;
#pragma unroll
        for (int u = 0; u < 4; u++)
            cp16(sm_u32(&WS40(wr, wc + u * 8)), Wrow + u * 8);
    }
    cp_wait();
    __syncthreads();

#pragma unroll
    for (int kk = 0; kk < 8; kk++) {
        unsigned af[2][4];
#pragma unroll
        for (int mi = 0; mi < 2; mi++) {
            int r = wm * 32 + mi * 16 + (lane & 15);
            int kh = kk * 16 + (lane >> 4) * 8;
            ldm_x4(af[mi], sm_u32(&AS(r, kh)));
        }
        unsigned bf[4][2];
#pragma unroll
        for (int nt = 0; nt < 2; nt++) {
            int g = lane >> 3, r = lane & 7;
            int krow = kk * 16 + (g & 1) * 8 + r;
            int ncol = wn * 32 + nt * 16 + (g >> 1) * 8;
            unsigned t[4];
            ldm_x4t(t, sm_u32(&WS40(krow, ncol)));
            bf[nt * 2 + 0][0] = t[0]; bf[nt * 2 + 0][1] = t[1];
            bf[nt * 2 + 1][0] = t[2]; bf[nt * 2 + 1][1] = t[3];
        }
#pragma unroll
        for (int mi = 0; mi < 2; mi++)
#pragma unroll
            for (int ni = 0; ni < 4; ni++)
                mma16816(acc[mi][ni], af[mi], bf[ni]);
    }

    const int r1 = lane >> 2;
    const int c2 = (lane & 3) * 2;
#pragma unroll
    for (int mi = 0; mi < 2; mi++) {
        int gr0 = row0 + wm * 32 + mi * 16 + r1;
        int gr1 = gr0 + 8;
        float d0 = (gr0 < n) ? g_dinv[gr0] : 0.f;
        float d1 = (gr1 < n) ? g_dinv[gr1] : 0.f;
#pragma unroll
        for (int ni = 0; ni < 4; ni++) {
            int col = wn * 32 + ni * 8 + c2;
            if (col >= 40) continue;
            if (gr0 < n) {
                __half2 h = __floats2half2_rn(acc[mi][ni][0] * d0,
                                              acc[mi][ni][1] * d0);
                *(unsigned*)(H2h + (size_t)gr0 * 40 + col) = *(unsigned*)&h;
            }
            if (gr1 < n) {
                __half2 h = __floats2half2_rn(acc[mi][ni][2] * d1,
                                              acc[mi][ni][3] * d1);
                *(unsigned*)(H2h + (size_t)gr1 * 40 + col) = *(unsigned*)&h;
            }
        }
    }
}

// ------------------------------------------------------------------
// SpMM (fp16 messages; self-loop + bias + RELU folded):
//   AGG[d] = half(relu(dinv[d] * (Hh[d] + sum Hh[s]) + b))
// also re-zeroes g_degi for the next graph replay
// ------------------------------------------------------------------
__global__ __launch_bounds__(256)
void k_spmm128(const __half* __restrict__ hh, __half* __restrict__ agg,
               const float* __restrict__ b, int n) {
    int w = (blockIdx.x * blockDim.x + threadIdx.x) >> 5;
    if (w >= n) return;
    int lane = threadIdx.x & 31;
    if (lane == 0) g_degi[w] = 0;
    int beg = g_rowptr[w];
    int end = g_cursor[w];
    float dd = g_dinv[w];
    uint2 us = *(const uint2*)(hh + (size_t)w * 128 + lane * 4);
    float2 s0 = __half22float2(*(const __half2*)&us.x);
    float2 s1 = __half22float2(*(const __half2*)&us.y);
    float4 acc = make_float4(s0.x, s0.y, s1.x, s1.y);

    int idx = beg;
    for (; idx + 8 <= end; idx += 8) {
        uint2 u[8];
#pragma unroll
        for (int q = 0; q < 8; q++) {
            int s = g_csr[idx + q];
            u[q] = *(const uint2*)(hh + (size_t)s * 128 + lane * 4);
        }
#pragma unroll
        for (int q = 0; q < 8; q++) {
            float2 f0 = __half22float2(*(const __half2*)&u[q].x);
            float2 f1 = __half22float2(*(const __half2*)&u[q].y);
            acc.x += f0.x; acc.y += f0.y; acc.z += f1.x; acc.w += f1.y;
        }
    }
    for (; idx < end; ++idx) {
        int s = g_csr[idx];
        uint2 u = *(const uint2*)(hh + (size_t)s * 128 + lane * 4);
        float2 f0 = __half22float2(*(const __half2*)&u.x);
        float2 f1 = __half22float2(*(const __half2*)&u.y);
        acc.x += f0.x; acc.y += f0.y; acc.z += f1.x; acc.w += f1.y;
    }
    float4 bv = *(const float4*)(b + lane * 4);
    float rx = fmaxf(dd * acc.x + bv.x, 0.f);
    float ry = fmaxf(dd * acc.y + bv.y, 0.f);
    float rz = fmaxf(dd * acc.z + bv.z, 0.f);
    float rw = fmaxf(dd * acc.w + bv.w, 0.f);
    __half2 r0 = __floats2half2_rn(rx, ry);
    __half2 r1 = __floats2half2_rn(rz, rw);
    uint2 res; res.x = *(unsigned*)&r0; res.y = *(unsigned*)&r1;
    *(uint2*)(agg + (size_t)w * 128 + lane * 4) = res;
}

// layer-2 final: OUT[d] = dinv[d] * (H2h[d] + sum H2h[s]) + b2 (fp32)
__global__ __launch_bounds__(256)
void k_spmm40h(const __half* __restrict__ hh, float* __restrict__ out,
               const float* __restrict__ b, int n) {
    int w = (blockIdx.x * blockDim.x + threadIdx.x) >> 5;
    if (w >= n) return;
    int lane = threadIdx.x & 31;
    if (lane >= 20) return;
    int beg = g_rowptr[w];
    int end = g_cursor[w];
    float dd = g_dinv[w];
    unsigned usf = *(const unsigned*)(hh + (size_t)w * 40 + lane * 2);
    float2 acc = __half22float2(*(const __half2*)&usf);

    int idx = beg;
    for (; idx + 4 <= end; idx += 4) {
        int i0 = g_csr[idx + 0], i1 = g_csr[idx + 1];
        int i2 = g_csr[idx + 2], i3 = g_csr[idx + 3];
        unsigned u0 = *(const unsigned*)(hh + (size_t)i0 * 40 + lane * 2);
        unsigned u1 = *(const unsigned*)(hh + (size_t)i1 * 40 + lane * 2);
        unsigned u2 = *(const unsigned*)(hh + (size_t)i2 * 40 + lane * 2);
        unsigned u3 = *(const unsigned*)(hh + (size_t)i3 * 40 + lane * 2);
        float2 f0 = __half22float2(*(const __half2*)&u0);
        float2 f1 = __half22float2(*(const __half2*)&u1);
        float2 f2 = __half22float2(*(const __half2*)&u2);
        float2 f3 = __half22float2(*(const __half2*)&u3);
        acc.x += f0.x + f1.x + f2.x + f3.x;
        acc.y += f0.y + f1.y + f2.y + f3.y;
    }
    for (; idx < end; ++idx) {
        int s = g_csr[idx];
        unsigned u = *(const unsigned*)(hh + (size_t)s * 40 + lane * 2);
        float2 f = __half22float2(*(const __half2*)&u);
        acc.x += f.x; acc.y += f.y;
    }
    float2 bv = *(const float2*)(b + lane * 2);
    float2 res = make_float2(dd * acc.x + bv.x, dd * acc.y + bv.y);
    *(float2*)(out + (size_t)w * 40 + lane * 2) = res;
}

// ------------------------------------------------------------------
extern "C" void kernel_launch(void* const* d_in, const int* in_sizes, int n_in,
                              void* d_out, int out_size) {
    const float* x  = (const float*)d_in[0];
    const float* W0 = (const float*)d_in[1];
    const float* b0 = (const float*)d_in[2];
    const float* W1 = (const float*)d_in[3];
    const float* b1 = (const float*)d_in[4];
    const float* W2 = (const float*)d_in[5];
    const float* b2 = (const float*)d_in[6];
    const void*  ei = d_in[7];
    int n = in_sizes[0] / FEAT;
    int E = in_sizes[7] / 2;
    if (E > EMAX) E = EMAX;
    float* out = (float*)d_out;

    __half *pHh, *pH2h, *pAGG, *pW0h, *pW1h;
    cudaGetSymbolAddress((void**)&pHh,  g_Hh);
    cudaGetSymbolAddress((void**)&pH2h, g_H2h);
    cudaGetSymbolAddress((void**)&pAGG, g_AGG);
    cudaGetSymbolAddress((void**)&pW0h, g_W0h);
    cudaGetSymbolAddress((void**)&pW1h, g_W1h);

    static cudaStream_t s2 = nullptr;
    static cudaEvent_t evStart = nullptr, evDinv = nullptr, evJoin = nullptr;
    static bool attrSet = false;
    if (!s2) {
        cudaStreamCreateWithFlags(&s2, cudaStreamNonBlocking);
        cudaEventCreateWithFlags(&evStart, cudaEventDisableTiming);
        cudaEventCreateWithFlags(&evDinv,  cudaEventDisableTiming);
        cudaEventCreateWithFlags(&evJoin,  cudaEventDisableTiming);
    }
    const int GSMEM   = 2 * 17408 * (int)sizeof(__half);           // 69632 B
    const int GSMEM40 = (17408 + 128 * 72) * (int)sizeof(__half);  // 53248 B
    if (!attrSet) {
        cudaFuncSetAttribute(k_gemm128h<false>,
                             cudaFuncAttributeMaxDynamicSharedMemorySize, GSMEM);
        cudaFuncSetAttribute(k_gemm128h<true>,
                             cudaFuncAttributeMaxDynamicSharedMemorySize, GSMEM);
        cudaFuncSetAttribute(k_gemm40h,
                             cudaFuncAttributeMaxDynamicSharedMemorySize, GSMEM40);
        attrSet = true;
    }

    const int tb = 256;
    int eblk = (E + tb - 1) / tb;
    int oblk = (n + 255) / 256;
    int gblk = (n + 127) / 128;
    int wblk = (int)(((long long)n * 32 + tb - 1) / tb);

    // ---- fork s2 early: convW is dependency-free ----
    cudaEventRecord(evStart, 0);
    cudaStreamWaitEvent(s2, evStart, 0);
    k_convW<<<(40960 + tb - 1) / tb, tb, 0, s2>>>(W0, W1, W2);

    // ---- main: degree -> offsets(dinv) ----
    k_count<<<eblk, tb>>>(ei, n, E);
    k_offset<<<oblk, 256>>>(n);
    cudaEventRecord(evDinv, 0);

    // ---- s2: layer-0 GEMM (needs convW + dinv) || main: fill ----
    cudaStreamWaitEvent(s2, evDinv, 0);
    k_gemm128h<false><<<gblk, 256, GSMEM, s2>>>(x, pW0h, pHh, n);
    cudaEventRecord(evJoin, s2);

    k_fill<<<eblk, tb>>>(ei, n, E);
    cudaStreamWaitEvent(0, evJoin, 0);

    // ---- pipeline ----
    k_spmm128<<<wblk, tb>>>(pHh, pAGG, b0, n);
    k_gemm128h<true><<<gblk, 256, GSMEM>>>(pAGG, pW1h, pHh, n);
    k_spmm128<<<wblk, tb>>>(pHh, pAGG, b1, n);
    k_gemm40h<<<gblk, 256, GSMEM40>>>(pAGG, pH2h, n);
    k_spmm40h<<<wblk, tb>>>(pH2h, out, b2, n);
}

// round 13
// speedup vs baseline: 1.0691x; 1.0691x over previous
#include <cuda_runtime.h>
#include <cuda_fp16.h>

#define NN    100000
#define FEAT  128
#define CLS   40
#define EMAX  1600000

// ---- scratch (static device globals; no allocation allowed) ----
__device__ int    g_degi[NN];                // zero at load; re-zeroed by k_offset
__device__ float  g_dinv[NN];
__device__ __half g_Hh[(size_t)NN * FEAT];   // pre-scaled fp16 messages h*dinv
__device__ __half g_AGG[(size_t)NN * FEAT];  // fp16 relu'd conv output
__device__ __half g_H2h[(size_t)NN * CLS];   // layer-2 pre-scaled fp16 messages
__device__ __half g_W0h[16384];
__device__ __half g_W1h[16384];
__device__ __half g_W2p[128 * 64];           // W2 padded 40->64 cols
__device__ int2   g_seg[NN];                 // x=segment start, y=cursor/end
__device__ int    g_csr[EMAX];
__device__ int    g_total;

// ---- helpers ----
__device__ __forceinline__ unsigned sm_u32(const void* p) {
    return (unsigned)__cvta_generic_to_shared(p);
}
__device__ __forceinline__ void ldm_x4(unsigned* r, unsigned a) {
    asm volatile("ldmatrix.sync.aligned.m8n8.x4.shared.b16 {%0,%1,%2,%3}, [%4];"
                 : "=r"(r[0]), "=r"(r[1]), "=r"(r[2]), "=r"(r[3]) : "r"(a));
}
__device__ __forceinline__ void ldm_x4t(unsigned* r, unsigned a) {
    asm volatile("ldmatrix.sync.aligned.m8n8.x4.trans.shared.b16 {%0,%1,%2,%3}, [%4];"
                 : "=r"(r[0]), "=r"(r[1]), "=r"(r[2]), "=r"(r[3]) : "r"(a));
}
__device__ __forceinline__ void mma16816(float* d, const unsigned* a,
                                         const unsigned* b) {
    asm volatile(
        "mma.sync.aligned.m16n8k16.row.col.f32.f16.f16.f32 "
        "{%0,%1,%2,%3},{%4,%5,%6,%7},{%8,%9},{%0,%1,%2,%3};"
        : "+f"(d[0]), "+f"(d[1]), "+f"(d[2]), "+f"(d[3])
        : "r"(a[0]), "r"(a[1]), "r"(a[2]), "r"(a[3]), "r"(b[0]), "r"(b[1]));
}
__device__ __forceinline__ void cp16(unsigned d, const void* s) {
    asm volatile("cp.async.ca.shared.global [%0], [%1], 16;" :: "r"(d), "l"(s));
}
__device__ __forceinline__ void cp16p(unsigned d, const void* s, bool p) {
    int sz = p ? 16 : 0;
    asm volatile("cp.async.ca.shared.global [%0], [%1], 16, %2;"
                 :: "r"(d), "l"(s), "r"(sz));
}
__device__ __forceinline__ void cp_commit() {
    asm volatile("cp.async.commit_group;" ::: "memory");
}
template <int N>
__device__ __forceinline__ void cp_waitg() {
    asm volatile("cp.async.wait_group %0;" :: "n"(N) : "memory");
}
__device__ __forceinline__ bool ei_is64(const void* ei, int n) {
    const unsigned long long* p = (const unsigned long long*)ei;
    return p[0] < (unsigned long long)n && p[1] < (unsigned long long)n;
}

// ------------------------------------------------------------------
// CSR build (unordered segments): count -> offset -> fill
// ------------------------------------------------------------------
__global__ void k_count(const void* ei, int n, int E) {
    if (blockIdx.x == 0 && threadIdx.x == 0) g_total = 0;
    int e = blockIdx.x * blockDim.x + threadIdx.x;
    if (e >= E) return;
    bool is64 = ei_is64(ei, n);
    int dst = is64 ? (int)((const long long*)ei)[E + e]
                   : ((const int*)ei)[E + e];
    atomicAdd(&g_degi[dst], 1);
}

// per-256-node block: local scan + atomic base; writes dinv; zeroes degi
__global__ void k_offset(int n) {
    __shared__ int wsum[8];
    __shared__ int base;
    int t = threadIdx.x;
    int i = blockIdx.x * 256 + t;
    int lane = t & 31, warp = t >> 5;
    int deg = (i < n) ? g_degi[i] : 0;
    if (i < n) {
        g_dinv[i] = rsqrtf((float)deg + 1.f);
        g_degi[i] = 0;                        // ready for next replay
    }
    int v = deg;
#pragma unroll
    for (int off = 1; off < 32; off <<= 1) {
        int x = __shfl_up_sync(0xffffffffu, v, off);
        if (lane >= off) v += x;
    }
    if (lane == 31) wsum[warp] = v;
    __syncthreads();
    if (warp == 0 && lane < 8) {
        int s = wsum[lane];
#pragma unroll
        for (int off = 1; off < 8; off <<= 1) {
            int x = __shfl_up_sync(0xffu, s, off);
            if (lane >= off) s += x;
        }
        wsum[lane] = s;
    }
    __syncthreads();
    if (t == 0) base = atomicAdd(&g_total, wsum[7]);
    __syncthreads();
    if (i < n) {
        int incl = v + (warp > 0 ? wsum[warp - 1] : 0);
        int r = base + incl - deg;
        g_seg[i] = make_int2(r, r);
    }
}

__global__ void k_fill(const void* ei, int n, int E) {
    int e = blockIdx.x * blockDim.x + threadIdx.x;
    if (e >= E) return;
    bool is64 = ei_is64(ei, n);
    int s, d;
    if (is64) {
        const long long* p = (const long long*)ei;
        s = (int)p[e]; d = (int)p[E + e];
    } else {
        const int* p = (const int*)ei;
        s = p[e]; d = p[E + e];
    }
    int pos = atomicAdd(&g_seg[d].y, 1);
    g_csr[pos] = s;
}

// weights -> fp16 (W2 padded 40->64)
__global__ void k_convW(const float* W0, const float* W1, const float* W2) {
    int i = blockIdx.x * blockDim.x + threadIdx.x;
    if (i < 16384) {
        g_W0h[i] = __float2half_rn(W0[i]);
    } else if (i < 32768) {
        g_W1h[i - 16384] = __float2half_rn(W1[i - 16384]);
    } else if (i < 32768 + 128 * 64) {
        int j = i - 32768;
        int k = j >> 6, c = j & 63;
        g_W2p[j] = __float2half_rn(c < 40 ? W2[k * 40 + c] : 0.f);
    }
}

// ------------------------------------------------------------------
// Tensor-core GEMM (K=128, Nout=128), 2-stage cp.async pipeline:
//   h  = A @ Wh ; Hh = half(h * dinv)
// stage s: A[:, 64s:64s+64) + W[64s:64s+64, :)
// ------------------------------------------------------------------
#define SPITCH 136
#define AS(r, c) dsm[(r) * SPITCH + (c)]
#define WS(r, c) dsm[17408 + (r) * SPITCH + (c)]
#define HS(r, c) dsm[(r) * SPITCH + (c)]

template <bool HIN>
__global__ __launch_bounds__(256)
void k_gemm128h(const void* __restrict__ A, const __half* __restrict__ Wh,
                __half* __restrict__ Hh, int n) {
    extern __shared__ __half dsm[];
    const int tid  = threadIdx.x;
    const int lane = tid & 31;
    const int warp = tid >> 5;
    const int wm   = warp & 3;
    const int wn   = warp >> 2;
    const int row0 = blockIdx.x * 128;

    float acc[2][8][4];
#pragma unroll
    for (int mi = 0; mi < 2; mi++)
#pragma unroll
        for (int ni = 0; ni < 8; ni++)
#pragma unroll
            for (int q = 0; q < 4; q++) acc[mi][ni][q] = 0.f;

    if (HIN) {
        // pipelined fp16 path: per stage, each thread does 4 A + 4 W cp16
        const int arow = tid >> 1;                 // A row 0..127
        const int acol = (tid & 1) * 32;           // col offset within stage
        const int wrow = tid >> 2;                 // W row within stage 0..63
        const int wcol = (tid & 3) * 32;
        int gr = row0 + arow;
        bool ok = gr < n;
        const __half* Arow = (const __half*)A + (size_t)gr * 128;
#pragma unroll
        for (int s = 0; s < 2; s++) {
            int ak = s * 64 + acol;
#pragma unroll
            for (int u = 0; u < 4; u++)
                cp16p(sm_u32(&AS(arow, ak + u * 8)), Arow + ak + u * 8, ok);
            const __half* Wrow = Wh + (size_t)(s * 64 + wrow) * 128 + wcol;
#pragma unroll
            for (int u = 0; u < 4; u++)
                cp16(sm_u32(&WS(s * 64 + wrow, wcol + u * 8)), Wrow + u * 8);
            cp_commit();
        }
        cp_waitg<1>();          // stage 0 landed
    } else {
        // fp32 convert path (layer 0): full load, no pipeline
        const int ar = tid >> 1, ac = (tid & 1) * 64;
        int gr = row0 + ar;
        const float* Arow = (const float*)A + (size_t)gr * 128 + ac;
#pragma unroll
        for (int u = 0; u < 8; u++) {
            float4 f0 = make_float4(0.f, 0.f, 0.f, 0.f), f1 = f0;
            if (gr < n) {
                f0 = *(const float4*)(Arow + u * 8);
                f1 = *(const float4*)(Arow + u * 8 + 4);
            }
            __half2 hh[4];
            hh[0] = __floats2half2_rn(f0.x, f0.y);
            hh[1] = __floats2half2_rn(f0.z, f0.w);
            hh[2] = __floats2half2_rn(f1.x, f1.y);
            hh[3] = __floats2half2_rn(f1.z, f1.w);
            *(uint4*)&AS(ar, ac + u * 8) = *(uint4*)hh;
        }
        const __half* Wrow = Wh + ar * 128 + ac;
#pragma unroll
        for (int u = 0; u < 8; u++)
            cp16(sm_u32(&WS(ar, ac + u * 8)), Wrow + u * 8);
        cp_commit();
        cp_waitg<0>();
    }
    __syncthreads();

#pragma unroll
    for (int half = 0; half < 2; half++) {
        if (HIN && half == 1) {
            cp_waitg<0>();      // stage 1 landed
            __syncthreads();
        }
#pragma unroll
        for (int kq = 0; kq < 4; kq++) {
            int kk = half * 4 + kq;
            unsigned af[2][4];
#pragma unroll
            for (int mi = 0; mi < 2; mi++) {
                int r = wm * 32 + mi * 16 + (lane & 15);
                int kh = kk * 16 + (lane >> 4) * 8;
                ldm_x4(af[mi], sm_u32(&AS(r, kh)));
            }
            unsigned bf[8][2];
#pragma unroll
            for (int nt = 0; nt < 4; nt++) {
                int g = lane >> 3, r = lane & 7;
                int krow = kk * 16 + (g & 1) * 8 + r;
                int ncol = wn * 64 + nt * 16 + (g >> 1) * 8;
                unsigned t[4];
                ldm_x4t(t, sm_u32(&WS(krow, ncol)));
                bf[nt * 2 + 0][0] = t[0]; bf[nt * 2 + 0][1] = t[1];
                bf[nt * 2 + 1][0] = t[2]; bf[nt * 2 + 1][1] = t[3];
            }
#pragma unroll
            for (int mi = 0; mi < 2; mi++)
#pragma unroll
                for (int ni = 0; ni < 8; ni++)
                    mma16816(acc[mi][ni], af[mi], bf[ni]);
        }
    }

    __syncthreads();
    {
        const int r1 = lane >> 2;
        const int c2 = (lane & 3) * 2;
#pragma unroll
        for (int mi = 0; mi < 2; mi++) {
            int r = wm * 32 + mi * 16 + r1;
#pragma unroll
            for (int ni = 0; ni < 8; ni++) {
                int col = wn * 64 + ni * 8 + c2;
                __half2 h01 = __floats2half2_rn(acc[mi][ni][0], acc[mi][ni][1]);
                __half2 h23 = __floats2half2_rn(acc[mi][ni][2], acc[mi][ni][3]);
                *(__half2*)&HS(r, col)     = h01;
                *(__half2*)&HS(r + 8, col) = h23;
            }
        }
    }
    __syncthreads();
    {
        int rrow  = tid >> 4;
        int chunk = tid & 15;
#pragma unroll
        for (int p = 0; p < 8; p++) {
            int r = p * 16 + rrow;
            int gr = row0 + r;
            if (gr < n) {
                __half2 d2 = __float2half2_rn(g_dinv[gr]);
                uint4 u = *(uint4*)&HS(r, chunk * 8);
                __half2* hp = (__half2*)&u;
                hp[0] = __hmul2(hp[0], d2); hp[1] = __hmul2(hp[1], d2);
                hp[2] = __hmul2(hp[2], d2); hp[3] = __hmul2(hp[3], d2);
                *(uint4*)(Hh + (size_t)gr * 128 + chunk * 8) = u;
            }
        }
    }
}

// ------------------------------------------------------------------
// Tensor-core GEMM (K=128, Nout=64 padded; 40 real), fp16 A + W, 2-stage:
//   h2 = A @ W2p ; H2h = half(h2 * dinv)
// ------------------------------------------------------------------
#define WS40(r, c) dsm[17408 + (r) * 72 + (c)]

__global__ __launch_bounds__(256)
void k_gemm40h(const __half* __restrict__ A, __half* __restrict__ H2h, int n) {
    extern __shared__ __half dsm[];
    const int tid  = threadIdx.x;
    const int lane = tid & 31;
    const int warp = tid >> 5;
    const int wm   = warp & 3;
    const int wn   = warp >> 2;
    const int row0 = blockIdx.x * 128;

    float acc[2][4][4];
#pragma unroll
    for (int mi = 0; mi < 2; mi++)
#pragma unroll
        for (int ni = 0; ni < 4; ni++)
#pragma unroll
            for (int q = 0; q < 4; q++) acc[mi][ni][q] = 0.f;

    {
        const int arow = tid >> 1;
        const int acol = (tid & 1) * 32;
        const int wrow = tid >> 2;              // 0..63
        const int wcol = (tid & 3) * 16;        // 64 cols / 4 threads
        int gr = row0 + arow;
        bool ok = gr < n;
        const __half* Arow = A + (size_t)gr * 128;
#pragma unroll
        for (int s = 0; s < 2; s++) {
            int ak = s * 64 + acol;
#pragma unroll
            for (int u = 0; u < 4; u++)
                cp16p(sm_u32(&AS(arow, ak + u * 8)), Arow + ak + u * 8, ok);
            const __half* Wrow = g_W2p + (size_t)(s * 64 + wrow) * 64 + wcol;
#pragma unroll
            for (int u = 0; u < 2; u++)
                cp16(sm_u32(&WS40(s * 64 + wrow, wcol + u * 8)), Wrow + u * 8);
            cp_commit();
        }
        cp_waitg<1>();
    }
    __syncthreads();

#pragma unroll
    for (int half = 0; half < 2; half++) {
        if (half == 1) {
            cp_waitg<0>();
            __syncthreads();
        }
#pragma unroll
        for (int kq = 0; kq < 4; kq++) {
            int kk = half * 4 + kq;
            unsigned af[2][4];
#pragma unroll
            for (int mi = 0; mi < 2; mi++) {
                int r = wm * 32 + mi * 16 + (lane & 15);
                int kh = kk * 16 + (lane >> 4) * 8;
                ldm_x4(af[mi], sm_u32(&AS(r, kh)));
            }
            unsigned bf[4][2];
#pragma unroll
            for (int nt = 0; nt < 2; nt++) {
                int g = lane >> 3, r = lane & 7;
                int krow = kk * 16 + (g & 1) * 8 + r;
                int ncol = wn * 32 + nt * 16 + (g >> 1) * 8;
                unsigned t[4];
                ldm_x4t(t, sm_u32(&WS40(krow, ncol)));
                bf[nt * 2 + 0][0] = t[0]; bf[nt * 2 + 0][1] = t[1];
                bf[nt * 2 + 1][0] = t[2]; bf[nt * 2 + 1][1] = t[3];
            }
#pragma unroll
            for (int mi = 0; mi < 2; mi++)
#pragma unroll
                for (int ni = 0; ni < 4; ni++)
                    mma16816(acc[mi][ni], af[mi], bf[ni]);
        }
    }

    const int r1 = lane >> 2;
    const int c2 = (lane & 3) * 2;
#pragma unroll
    for (int mi = 0; mi < 2; mi++) {
        int gr0 = row0 + wm * 32 + mi * 16 + r1;
        int gr1 = gr0 + 8;
        float d0 = (gr0 < n) ? g_dinv[gr0] : 0.f;
        float d1 = (gr1 < n) ? g_dinv[gr1] : 0.f;
#pragma unroll
        for (int ni = 0; ni < 4; ni++) {
            int col = wn * 32 + ni * 8 + c2;
            if (col >= 40) continue;
            if (gr0 < n) {
                __half2 h = __floats2half2_rn(acc[mi][ni][0] * d0,
                                              acc[mi][ni][1] * d0);
                *(unsigned*)(H2h + (size_t)gr0 * 40 + col) = *(unsigned*)&h;
            }
            if (gr1 < n) {
                __half2 h = __floats2half2_rn(acc[mi][ni][2] * d1,
                                              acc[mi][ni][3] * d1);
                *(unsigned*)(H2h + (size_t)gr1 * 40 + col) = *(unsigned*)&h;
            }
        }
    }
}

// ------------------------------------------------------------------
// SpMM (fp16 messages; self-loop + bias + RELU folded):
//   AGG[d] = half(relu(dinv[d] * (Hh[d] + sum Hh[s]) + b))
// ------------------------------------------------------------------
__global__ __launch_bounds__(256)
void k_spmm128(const __half* __restrict__ hh, __half* __restrict__ agg,
               const float* __restrict__ b, int n) {
    int w = (blockIdx.x * blockDim.x + threadIdx.x) >> 5;
    if (w >= n) return;
    int lane = threadIdx.x & 31;
    int2 se = g_seg[w];
    float dd = g_dinv[w];
    uint2 us = *(const uint2*)(hh + (size_t)w * 128 + lane * 4);
    float2 s0 = __half22float2(*(const __half2*)&us.x);
    float2 s1 = __half22float2(*(const __half2*)&us.y);
    float4 acc = make_float4(s0.x, s0.y, s1.x, s1.y);

    int idx = se.x;
    int end = se.y;
    for (; idx + 8 <= end; idx += 8) {
        uint2 u[8];
#pragma unroll
        for (int q = 0; q < 8; q++) {
            int s = g_csr[idx + q];
            u[q] = *(const uint2*)(hh + (size_t)s * 128 + lane * 4);
        }
#pragma unroll
        for (int q = 0; q < 8; q++) {
            float2 f0 = __half22float2(*(const __half2*)&u[q].x);
            float2 f1 = __half22float2(*(const __half2*)&u[q].y);
            acc.x += f0.x; acc.y += f0.y; acc.z += f1.x; acc.w += f1.y;
        }
    }
    for (; idx < end; ++idx) {
        int s = g_csr[idx];
        uint2 u = *(const uint2*)(hh + (size_t)s * 128 + lane * 4);
        float2 f0 = __half22float2(*(const __half2*)&u.x);
        float2 f1 = __half22float2(*(const __half2*)&u.y);
        acc.x += f0.x; acc.y += f0.y; acc.z += f1.x; acc.w += f1.y;
    }
    float4 bv = *(const float4*)(b + lane * 4);
    float rx = fmaxf(dd * acc.x + bv.x, 0.f);
    float ry = fmaxf(dd * acc.y + bv.y, 0.f);
    float rz = fmaxf(dd * acc.z + bv.z, 0.f);
    float rw = fmaxf(dd * acc.w + bv.w, 0.f);
    __half2 r0 = __floats2half2_rn(rx, ry);
    __half2 r1 = __floats2half2_rn(rz, rw);
    uint2 res; res.x = *(unsigned*)&r0; res.y = *(unsigned*)&r1;
    *(uint2*)(agg + (size_t)w * 128 + lane * 4) = res;
}

// layer-2 final: OUT[d] = dinv[d] * (H2h[d] + sum H2h[s]) + b2 (fp32)
__global__ __launch_bounds__(256)
void k_spmm40h(const __half* __restrict__ hh, float* __restrict__ out,
               const float* __restrict__ b, int n) {
    int w = (blockIdx.x * blockDim.x + threadIdx.x) >> 5;
    if (w >= n) return;
    int lane = threadIdx.x & 31;
    if (lane >= 20) return;
    int2 se = g_seg[w];
    float dd = g_dinv[w];
    unsigned usf = *(const unsigned*)(hh + (size_t)w * 40 + lane * 2);
    float2 acc = __half22float2(*(const __half2*)&usf);

    int idx = se.x;
    int end = se.y;
    for (; idx + 4 <= end; idx += 4) {
        int i0 = g_csr[idx + 0], i1 = g_csr[idx + 1];
        int i2 = g_csr[idx + 2], i3 = g_csr[idx + 3];
        unsigned u0 = *(const unsigned*)(hh + (size_t)i0 * 40 + lane * 2);
        unsigned u1 = *(const unsigned*)(hh + (size_t)i1 * 40 + lane * 2);
        unsigned u2 = *(const unsigned*)(hh + (size_t)i2 * 40 + lane * 2);
        unsigned u3 = *(const unsigned*)(hh + (size_t)i3 * 40 + lane * 2);
        float2 f0 = __half22float2(*(const __half2*)&u0);
        float2 f1 = __half22float2(*(const __half2*)&u1);
        float2 f2 = __half22float2(*(const __half2*)&u2);
        float2 f3 = __half22float2(*(const __half2*)&u3);
        acc.x += f0.x + f1.x + f2.x + f3.x;
        acc.y += f0.y + f1.y + f2.y + f3.y;
    }
    for (; idx < end; ++idx) {
        int s = g_csr[idx];
        unsigned u = *(const unsigned*)(hh + (size_t)s * 40 + lane * 2);
        float2 f = __half22float2(*(const __half2*)&u);
        acc.x += f.x; acc.y += f.y;
    }
    float2 bv = *(const float2*)(b + lane * 2);
    float2 res = make_float2(dd * acc.x + bv.x, dd * acc.y + bv.y);
    *(float2*)(out + (size_t)w * 40 + lane * 2) = res;
}

// ------------------------------------------------------------------
extern "C" void kernel_launch(void* const* d_in, const int* in_sizes, int n_in,
                              void* d_out, int out_size) {
    const float* x  = (const float*)d_in[0];
    const float* W0 = (const float*)d_in[1];
    const float* b0 = (const float*)d_in[2];
    const float* W1 = (const float*)d_in[3];
    const float* b1 = (const float*)d_in[4];
    const float* W2 = (const float*)d_in[5];
    const float* b2 = (const float*)d_in[6];
    const void*  ei = d_in[7];
    int n = in_sizes[0] / FEAT;
    int E = in_sizes[7] / 2;
    if (E > EMAX) E = EMAX;
    float* out = (float*)d_out;

    __half *pHh, *pH2h, *pAGG, *pW0h, *pW1h;
    cudaGetSymbolAddress((void**)&pHh,  g_Hh);
    cudaGetSymbolAddress((void**)&pH2h, g_H2h);
    cudaGetSymbolAddress((void**)&pAGG, g_AGG);
    cudaGetSymbolAddress((void**)&pW0h, g_W0h);
    cudaGetSymbolAddress((void**)&pW1h, g_W1h);

    static cudaStream_t s2 = nullptr;
    static cudaEvent_t evStart = nullptr, evDinv = nullptr, evJoin = nullptr;
    static bool attrSet = false;
    if (!s2) {
        cudaStreamCreateWithFlags(&s2, cudaStreamNonBlocking);
        cudaEventCreateWithFlags(&evStart, cudaEventDisableTiming);
        cudaEventCreateWithFlags(&evDinv,  cudaEventDisableTiming);
        cudaEventCreateWithFlags(&evJoin,  cudaEventDisableTiming);
    }
    const int GSMEM   = 2 * 17408 * (int)sizeof(__half);           // 69632 B
    const int GSMEM40 = (17408 + 128 * 72) * (int)sizeof(__half);  // 53248 B
    if (!attrSet) {
        cudaFuncSetAttribute(k_gemm128h<false>,
                             cudaFuncAttributeMaxDynamicSharedMemorySize, GSMEM);
        cudaFuncSetAttribute(k_gemm128h<true>,
                             cudaFuncAttributeMaxDynamicSharedMemorySize, GSMEM);
        cudaFuncSetAttribute(k_gemm40h,
                             cudaFuncAttributeMaxDynamicSharedMemorySize, GSMEM40);
        attrSet = true;
    }

    const int tb = 256;
    int eblk = (E + tb - 1) / tb;
    int oblk = (n + 255) / 256;
    int gblk = (n + 127) / 128;
    int wblk = (int)(((long long)n * 32 + tb - 1) / tb);

    // ---- fork s2 early: convW is dependency-free ----
    cudaEventRecord(evStart, 0);
    cudaStreamWaitEvent(s2, evStart, 0);
    k_convW<<<(40960 + tb - 1) / tb, tb, 0, s2>>>(W0, W1, W2);

    // ---- main: degree -> offsets(dinv) ----
    k_count<<<eblk, tb>>>(ei, n, E);
    k_offset<<<oblk, 256>>>(n);
    cudaEventRecord(evDinv, 0);

    // ---- s2: layer-0 GEMM (needs convW + dinv) || main: fill ----
    cudaStreamWaitEvent(s2, evDinv, 0);
    k_gemm128h<false><<<gblk, 256, GSMEM, s2>>>(x, pW0h, pHh, n);
    cudaEventRecord(evJoin, s2);

    k_fill<<<eblk, tb>>>(ei, n, E);
    cudaStreamWaitEvent(0, evJoin, 0);

    // ---- pipeline ----
    k_spmm128<<<wblk, tb>>>(pHh, pAGG, b0, n);
    k_gemm128h<true><<<gblk, 256, GSMEM>>>(pAGG, pW1h, pHh, n);
    k_spmm128<<<wblk, tb>>>(pHh, pAGG, b1, n);
    k_gemm40h<<<gblk, 256, GSMEM40>>>(pAGG, pH2h, n);
    k_spmm40h<<<wblk, tb>>>(pH2h, out, b2, n);
}

// round 14
// speedup vs baseline: 1.1116x; 1.0397x over previous
#include <cuda_runtime.h>
#include <cuda_fp16.h>

#define NN    100000
#define FEAT  128
#define CLS   40
#define EMAX  1600000

// ---- scratch (static device globals; no allocation allowed) ----
__device__ int    g_degi[NN];                // zero at load; re-zeroed by k_offset
__device__ float  g_dinv[NN];
__device__ __half g_Xh[(size_t)NN * FEAT];   // fp16 copy of input x
__device__ __half g_Hh[(size_t)NN * FEAT];   // pre-scaled fp16 messages h*dinv
__device__ __half g_AGG[(size_t)NN * FEAT];  // fp16 relu'd conv output
__device__ __half g_H2h[(size_t)NN * CLS];   // layer-2 pre-scaled fp16 messages
__device__ __half g_W0h[16384];
__device__ __half g_W1h[16384];
__device__ __half g_W2p[128 * 64];           // W2 padded 40->64 cols
__device__ int2   g_seg[NN];                 // x=segment start, y=cursor/end
__device__ int    g_csr[EMAX];
__device__ int    g_total;

// ---- helpers ----
__device__ __forceinline__ unsigned sm_u32(const void* p) {
    return (unsigned)__cvta_generic_to_shared(p);
}
__device__ __forceinline__ void ldm_x4(unsigned* r, unsigned a) {
    asm volatile("ldmatrix.sync.aligned.m8n8.x4.shared.b16 {%0,%1,%2,%3}, [%4];"
                 : "=r"(r[0]), "=r"(r[1]), "=r"(r[2]), "=r"(r[3]) : "r"(a));
}
__device__ __forceinline__ void ldm_x4t(unsigned* r, unsigned a) {
    asm volatile("ldmatrix.sync.aligned.m8n8.x4.trans.shared.b16 {%0,%1,%2,%3}, [%4];"
                 : "=r"(r[0]), "=r"(r[1]), "=r"(r[2]), "=r"(r[3]) : "r"(a));
}
__device__ __forceinline__ void mma16816(float* d, const unsigned* a,
                                         const unsigned* b) {
    asm volatile(
        "mma.sync.aligned.m16n8k16.row.col.f32.f16.f16.f32 "
        "{%0,%1,%2,%3},{%4,%5,%6,%7},{%8,%9},{%0,%1,%2,%3};"
        : "+f"(d[0]), "+f"(d[1]), "+f"(d[2]), "+f"(d[3])
        : "r"(a[0]), "r"(a[1]), "r"(a[2]), "r"(a[3]), "r"(b[0]), "r"(b[1]));
}
__device__ __forceinline__ void cp16(unsigned d, const void* s) {
    asm volatile("cp.async.ca.shared.global [%0], [%1], 16;" :: "r"(d), "l"(s));
}
__device__ __forceinline__ void cp16p(unsigned d, const void* s, bool p) {
    int sz = p ? 16 : 0;
    asm volatile("cp.async.ca.shared.global [%0], [%1], 16, %2;"
                 :: "r"(d), "l"(s), "r"(sz));
}
__device__ __forceinline__ void cp_commit() {
    asm volatile("cp.async.commit_group;" ::: "memory");
}
template <int N>
__device__ __forceinline__ void cp_waitg() {
    asm volatile("cp.async.wait_group %0;" :: "n"(N) : "memory");
}
__device__ __forceinline__ bool ei_is64(const void* ei, int n) {
    const unsigned long long* p = (const unsigned long long*)ei;
    return p[0] < (unsigned long long)n && p[1] < (unsigned long long)n;
}

// ------------------------------------------------------------------
// CSR build (unordered segments): count -> offset -> fill
// ------------------------------------------------------------------
__global__ void k_count(const void* ei, int n, int E) {
    if (blockIdx.x == 0 && threadIdx.x == 0) g_total = 0;
    int e = blockIdx.x * blockDim.x + threadIdx.x;
    if (e >= E) return;
    bool is64 = ei_is64(ei, n);
    int dst = is64 ? (int)((const long long*)ei)[E + e]
                   : ((const int*)ei)[E + e];
    atomicAdd(&g_degi[dst], 1);
}

// per-256-node block: local scan + atomic base; writes dinv; zeroes degi
__global__ void k_offset(int n) {
    __shared__ int wsum[8];
    __shared__ int base;
    int t = threadIdx.x;
    int i = blockIdx.x * 256 + t;
    int lane = t & 31, warp = t >> 5;
    int deg = (i < n) ? g_degi[i] : 0;
    if (i < n) {
        g_dinv[i] = rsqrtf((float)deg + 1.f);
        g_degi[i] = 0;
    }
    int v = deg;
#pragma unroll
    for (int off = 1; off < 32; off <<= 1) {
        int x = __shfl_up_sync(0xffffffffu, v, off);
        if (lane >= off) v += x;
    }
    if (lane == 31) wsum[warp] = v;
    __syncthreads();
    if (warp == 0 && lane < 8) {
        int s = wsum[lane];
#pragma unroll
        for (int off = 1; off < 8; off <<= 1) {
            int x = __shfl_up_sync(0xffu, s, off);
            if (lane >= off) s += x;
        }
        wsum[lane] = s;
    }
    __syncthreads();
    if (t == 0) base = atomicAdd(&g_total, wsum[7]);
    __syncthreads();
    if (i < n) {
        int incl = v + (warp > 0 ? wsum[warp - 1] : 0);
        int r = base + incl - deg;
        g_seg[i] = make_int2(r, r);
    }
}

__global__ void k_fill(const void* ei, int n, int E) {
    int e = blockIdx.x * blockDim.x + threadIdx.x;
    if (e >= E) return;
    bool is64 = ei_is64(ei, n);
    int s, d;
    if (is64) {
        const long long* p = (const long long*)ei;
        s = (int)p[e]; d = (int)p[E + e];
    } else {
        const int* p = (const int*)ei;
        s = p[e]; d = p[E + e];
    }
    int pos = atomicAdd(&g_seg[d].y, 1);
    g_csr[pos] = s;
}

// x -> fp16 (vectorized: 8 floats in, 8 halves out per thread)
__global__ void k_convX(const float* __restrict__ x, int total8) {
    int i = blockIdx.x * blockDim.x + threadIdx.x;
    if (i >= total8) return;
    const float4* src = (const float4*)(x + (size_t)i * 8);
    float4 f0 = src[0], f1 = src[1];
    __half2 hh[4];
    hh[0] = __floats2half2_rn(f0.x, f0.y);
    hh[1] = __floats2half2_rn(f0.z, f0.w);
    hh[2] = __floats2half2_rn(f1.x, f1.y);
    hh[3] = __floats2half2_rn(f1.z, f1.w);
    *(uint4*)(g_Xh + (size_t)i * 8) = *(uint4*)hh;
}

// weights -> fp16 (W2 padded 40->64)
__global__ void k_convW(const float* W0, const float* W1, const float* W2) {
    int i = blockIdx.x * blockDim.x + threadIdx.x;
    if (i < 16384) {
        g_W0h[i] = __float2half_rn(W0[i]);
    } else if (i < 32768) {
        g_W1h[i - 16384] = __float2half_rn(W1[i - 16384]);
    } else if (i < 32768 + 128 * 64) {
        int j = i - 32768;
        int k = j >> 6, c = j & 63;
        g_W2p[j] = __float2half_rn(c < 40 ? W2[k * 40 + c] : 0.f);
    }
}

// ------------------------------------------------------------------
// Tensor-core GEMM (K=128, Nout=128), 2-stage cp.async pipeline, fp16 in:
//   h  = A @ Wh ; Hh = half(h * dinv)
// ------------------------------------------------------------------
#define SPITCH 136
#define AS(r, c) dsm[(r) * SPITCH + (c)]
#define WS(r, c) dsm[17408 + (r) * SPITCH + (c)]
#define HS(r, c) dsm[(r) * SPITCH + (c)]

__global__ __launch_bounds__(256)
void k_gemm128h(const __half* __restrict__ A, const __half* __restrict__ Wh,
                __half* __restrict__ Hh, int n) {
    extern __shared__ __half dsm[];
    const int tid  = threadIdx.x;
    const int lane = tid & 31;
    const int warp = tid >> 5;
    const int wm   = warp & 3;
    const int wn   = warp >> 2;
    const int row0 = blockIdx.x * 128;

    float acc[2][8][4];
#pragma unroll
    for (int mi = 0; mi < 2; mi++)
#pragma unroll
        for (int ni = 0; ni < 8; ni++)
#pragma unroll
            for (int q = 0; q < 4; q++) acc[mi][ni][q] = 0.f;

    {
        const int arow = tid >> 1;
        const int acol = (tid & 1) * 32;
        const int wrow = tid >> 2;
        const int wcol = (tid & 3) * 32;
        int gr = row0 + arow;
        bool ok = gr < n;
        const __half* Arow = A + (size_t)gr * 128;
#pragma unroll
        for (int s = 0; s < 2; s++) {
            int ak = s * 64 + acol;
#pragma unroll
            for (int u = 0; u < 4; u++)
                cp16p(sm_u32(&AS(arow, ak + u * 8)), Arow + ak + u * 8, ok);
            const __half* Wrow = Wh + (size_t)(s * 64 + wrow) * 128 + wcol;
#pragma unroll
            for (int u = 0; u < 4; u++)
                cp16(sm_u32(&WS(s * 64 + wrow, wcol + u * 8)), Wrow + u * 8);
            cp_commit();
        }
        cp_waitg<1>();
    }
    __syncthreads();

#pragma unroll
    for (int half = 0; half < 2; half++) {
        if (half == 1) {
            cp_waitg<0>();
            __syncthreads();
        }
#pragma unroll
        for (int kq = 0; kq < 4; kq++) {
            int kk = half * 4 + kq;
            unsigned af[2][4];
#pragma unroll
            for (int mi = 0; mi < 2; mi++) {
                int r = wm * 32 + mi * 16 + (lane & 15);
                int kh = kk * 16 + (lane >> 4) * 8;
                ldm_x4(af[mi], sm_u32(&AS(r, kh)));
            }
            unsigned bf[8][2];
#pragma unroll
            for (int nt = 0; nt < 4; nt++) {
                int g = lane >> 3, r = lane & 7;
                int krow = kk * 16 + (g & 1) * 8 + r;
                int ncol = wn * 64 + nt * 16 + (g >> 1) * 8;
                unsigned t[4];
                ldm_x4t(t, sm_u32(&WS(krow, ncol)));
                bf[nt * 2 + 0][0] = t[0]; bf[nt * 2 + 0][1] = t[1];
                bf[nt * 2 + 1][0] = t[2]; bf[nt * 2 + 1][1] = t[3];
            }
#pragma unroll
            for (int mi = 0; mi < 2; mi++)
#pragma unroll
                for (int ni = 0; ni < 8; ni++)
                    mma16816(acc[mi][ni], af[mi], bf[ni]);
        }
    }

    __syncthreads();
    {
        const int r1 = lane >> 2;
        const int c2 = (lane & 3) * 2;
#pragma unroll
        for (int mi = 0; mi < 2; mi++) {
            int r = wm * 32 + mi * 16 + r1;
#pragma unroll
            for (int ni = 0; ni < 8; ni++) {
                int col = wn * 64 + ni * 8 + c2;
                __half2 h01 = __floats2half2_rn(acc[mi][ni][0], acc[mi][ni][1]);
                __half2 h23 = __floats2half2_rn(acc[mi][ni][2], acc[mi][ni][3]);
                *(__half2*)&HS(r, col)     = h01;
                *(__half2*)&HS(r + 8, col) = h23;
            }
        }
    }
    __syncthreads();
    {
        int rrow  = tid >> 4;
        int chunk = tid & 15;
#pragma unroll
        for (int p = 0; p < 8; p++) {
            int r = p * 16 + rrow;
            int gr = row0 + r;
            if (gr < n) {
                __half2 d2 = __float2half2_rn(g_dinv[gr]);
                uint4 u = *(uint4*)&HS(r, chunk * 8);
                __half2* hp = (__half2*)&u;
                hp[0] = __hmul2(hp[0], d2); hp[1] = __hmul2(hp[1], d2);
                hp[2] = __hmul2(hp[2], d2); hp[3] = __hmul2(hp[3], d2);
                *(uint4*)(Hh + (size_t)gr * 128 + chunk * 8) = u;
            }
        }
    }
}

// ------------------------------------------------------------------
// Tensor-core GEMM (K=128, Nout=64 padded; 40 real), fp16 A + W, 2-stage:
//   h2 = A @ W2p ; H2h = half(h2 * dinv)
// ------------------------------------------------------------------
#define WS40(r, c) dsm[17408 + (r) * 72 + (c)]

__global__ __launch_bounds__(256)
void k_gemm40h(const __half* __restrict__ A, __half* __restrict__ H2h, int n) {
    extern __shared__ __half dsm[];
    const int tid  = threadIdx.x;
    const int lane = tid & 31;
    const int warp = tid >> 5;
    const int wm   = warp & 3;
    const int wn   = warp >> 2;
    const int row0 = blockIdx.x * 128;

    float acc[2][4][4];
#pragma unroll
    for (int mi = 0; mi < 2; mi++)
#pragma unroll
        for (int ni = 0; ni < 4; ni++)
#pragma unroll
            for (int q = 0; q < 4; q++) acc[mi][ni][q] = 0.f;

    {
        const int arow = tid >> 1;
        const int acol = (tid & 1) * 32;
        const int wrow = tid >> 2;
        const int wcol = (tid & 3) * 16;
        int gr = row0 + arow;
        bool ok = gr < n;
        const __half* Arow = A + (size_t)gr * 128;
#pragma unroll
        for (int s = 0; s < 2; s++) {
            int ak = s * 64 + acol;
#pragma unroll
            for (int u = 0; u < 4; u++)
                cp16p(sm_u32(&AS(arow, ak + u * 8)), Arow + ak + u * 8, ok);
            const __half* Wrow = g_W2p + (size_t)(s * 64 + wrow) * 64 + wcol;
#pragma unroll
            for (int u = 0; u < 2; u++)
                cp16(sm_u32(&WS40(s * 64 + wrow, wcol + u * 8)), Wrow + u * 8);
            cp_commit();
        }
        cp_waitg<1>();
    }
    __syncthreads();

#pragma unroll
    for (int half = 0; half < 2; half++) {
        if (half == 1) {
            cp_waitg<0>();
            __syncthreads();
        }
#pragma unroll
        for (int kq = 0; kq < 4; kq++) {
            int kk = half * 4 + kq;
            unsigned af[2][4];
#pragma unroll
            for (int mi = 0; mi < 2; mi++) {
                int r = wm * 32 + mi * 16 + (lane & 15);
                int kh = kk * 16 + (lane >> 4) * 8;
                ldm_x4(af[mi], sm_u32(&AS(r, kh)));
            }
            unsigned bf[4][2];
#pragma unroll
            for (int nt = 0; nt < 2; nt++) {
                int g = lane >> 3, r = lane & 7;
                int krow = kk * 16 + (g & 1) * 8 + r;
                int ncol = wn * 32 + nt * 16 + (g >> 1) * 8;
                unsigned t[4];
                ldm_x4t(t, sm_u32(&WS40(krow, ncol)));
                bf[nt * 2 + 0][0] = t[0]; bf[nt * 2 + 0][1] = t[1];
                bf[nt * 2 + 1][0] = t[2]; bf[nt * 2 + 1][1] = t[3];
            }
#pragma unroll
            for (int mi = 0; mi < 2; mi++)
#pragma unroll
                for (int ni = 0; ni < 4; ni++)
                    mma16816(acc[mi][ni], af[mi], bf[ni]);
        }
    }

    const int r1 = lane >> 2;
    const int c2 = (lane & 3) * 2;
#pragma unroll
    for (int mi = 0; mi < 2; mi++) {
        int gr0 = row0 + wm * 32 + mi * 16 + r1;
        int gr1 = gr0 + 8;
        float d0 = (gr0 < n) ? g_dinv[gr0] : 0.f;
        float d1 = (gr1 < n) ? g_dinv[gr1] : 0.f;
#pragma unroll
        for (int ni = 0; ni < 4; ni++) {
            int col = wn * 32 + ni * 8 + c2;
            if (col >= 40) continue;
            if (gr0 < n) {
                __half2 h = __floats2half2_rn(acc[mi][ni][0] * d0,
                                              acc[mi][ni][1] * d0);
                *(unsigned*)(H2h + (size_t)gr0 * 40 + col) = *(unsigned*)&h;
            }
            if (gr1 < n) {
                __half2 h = __floats2half2_rn(acc[mi][ni][2] * d1,
                                              acc[mi][ni][3] * d1);
                *(unsigned*)(H2h + (size_t)gr1 * 40 + col) = *(unsigned*)&h;
            }
        }
    }
}

// ------------------------------------------------------------------
// SpMM (fp16 messages; self-loop + bias + RELU folded):
//   AGG[d] = half(relu(dinv[d] * (Hh[d] + sum Hh[s]) + b))
// ------------------------------------------------------------------
__global__ __launch_bounds__(256)
void k_spmm128(const __half* __restrict__ hh, __half* __restrict__ agg,
               const float* __restrict__ b, int n) {
    int w = (blockIdx.x * blockDim.x + threadIdx.x) >> 5;
    if (w >= n) return;
    int lane = threadIdx.x & 31;
    int2 se = g_seg[w];
    float dd = g_dinv[w];
    uint2 us = *(const uint2*)(hh + (size_t)w * 128 + lane * 4);
    float2 s0 = __half22float2(*(const __half2*)&us.x);
    float2 s1 = __half22float2(*(const __half2*)&us.y);
    float4 acc = make_float4(s0.x, s0.y, s1.x, s1.y);

    int idx = se.x;
    int end = se.y;
    for (; idx + 8 <= end; idx += 8) {
        uint2 u[8];
#pragma unroll
        for (int q = 0; q < 8; q++) {
            int s = g_csr[idx + q];
            u[q] = *(const uint2*)(hh + (size_t)s * 128 + lane * 4);
        }
#pragma unroll
        for (int q = 0; q < 8; q++) {
            float2 f0 = __half22float2(*(const __half2*)&u[q].x);
            float2 f1 = __half22float2(*(const __half2*)&u[q].y);
            acc.x += f0.x; acc.y += f0.y; acc.z += f1.x; acc.w += f1.y;
        }
    }
    for (; idx < end; ++idx) {
        int s = g_csr[idx];
        uint2 u = *(const uint2*)(hh + (size_t)s * 128 + lane * 4);
        float2 f0 = __half22float2(*(const __half2*)&u.x);
        float2 f1 = __half22float2(*(const __half2*)&u.y);
        acc.x += f0.x; acc.y += f0.y; acc.z += f1.x; acc.w += f1.y;
    }
    float4 bv = *(const float4*)(b + lane * 4);
    float rx = fmaxf(dd * acc.x + bv.x, 0.f);
    float ry = fmaxf(dd * acc.y + bv.y, 0.f);
    float rz = fmaxf(dd * acc.z + bv.z, 0.f);
    float rw = fmaxf(dd * acc.w + bv.w, 0.f);
    __half2 r0 = __floats2half2_rn(rx, ry);
    __half2 r1 = __floats2half2_rn(rz, rw);
    uint2 res; res.x = *(unsigned*)&r0; res.y = *(unsigned*)&r1;
    *(uint2*)(agg + (size_t)w * 128 + lane * 4) = res;
}

// layer-2 final: OUT[d] = dinv[d] * (H2h[d] + sum H2h[s]) + b2 (fp32)
__global__ __launch_bounds__(256)
void k_spmm40h(const __half* __restrict__ hh, float* __restrict__ out,
               const float* __restrict__ b, int n) {
    int w = (blockIdx.x * blockDim.x + threadIdx.x) >> 5;
    if (w >= n) return;
    int lane = threadIdx.x & 31;
    if (lane >= 20) return;
    int2 se = g_seg[w];
    float dd = g_dinv[w];
    unsigned usf = *(const unsigned*)(hh + (size_t)w * 40 + lane * 2);
    float2 acc = __half22float2(*(const __half2*)&usf);

    int idx = se.x;
    int end = se.y;
    for (; idx + 4 <= end; idx += 4) {
        int i0 = g_csr[idx + 0], i1 = g_csr[idx + 1];
        int i2 = g_csr[idx + 2], i3 = g_csr[idx + 3];
        unsigned u0 = *(const unsigned*)(hh + (size_t)i0 * 40 + lane * 2);
        unsigned u1 = *(const unsigned*)(hh + (size_t)i1 * 40 + lane * 2);
        unsigned u2 = *(const unsigned*)(hh + (size_t)i2 * 40 + lane * 2);
        unsigned u3 = *(const unsigned*)(hh + (size_t)i3 * 40 + lane * 2);
        float2 f0 = __half22float2(*(const __half2*)&u0);
        float2 f1 = __half22float2(*(const __half2*)&u1);
        float2 f2 = __half22float2(*(const __half2*)&u2);
        float2 f3 = __half22float2(*(const __half2*)&u3);
        acc.x += f0.x + f1.x + f2.x + f3.x;
        acc.y += f0.y + f1.y + f2.y + f3.y;
    }
    for (; idx < end; ++idx) {
        int s = g_csr[idx];
        unsigned u = *(const unsigned*)(hh + (size_t)s * 40 + lane * 2);
        float2 f = __half22float2(*(const __half2*)&u);
        acc.x += f.x; acc.y += f.y;
    }
    float2 bv = *(const float2*)(b + lane * 2);
    float2 res = make_float2(dd * acc.x + bv.x, dd * acc.y + bv.y);
    *(float2*)(out + (size_t)w * 40 + lane * 2) = res;
}

// ------------------------------------------------------------------
extern "C" void kernel_launch(void* const* d_in, const int* in_sizes, int n_in,
                              void* d_out, int out_size) {
    const float* x  = (const float*)d_in[0];
    const float* W0 = (const float*)d_in[1];
    const float* b0 = (const float*)d_in[2];
    const float* W1 = (const float*)d_in[3];
    const float* b1 = (const float*)d_in[4];
    const float* W2 = (const float*)d_in[5];
    const float* b2 = (const float*)d_in[6];
    const void*  ei = d_in[7];
    int n = in_sizes[0] / FEAT;
    int E = in_sizes[7] / 2;
    if (E > EMAX) E = EMAX;
    float* out = (float*)d_out;

    __half *pXh, *pHh, *pH2h, *pAGG, *pW0h, *pW1h;
    cudaGetSymbolAddress((void**)&pXh,  g_Xh);
    cudaGetSymbolAddress((void**)&pHh,  g_Hh);
    cudaGetSymbolAddress((void**)&pH2h, g_H2h);
    cudaGetSymbolAddress((void**)&pAGG, g_AGG);
    cudaGetSymbolAddress((void**)&pW0h, g_W0h);
    cudaGetSymbolAddress((void**)&pW1h, g_W1h);

    static cudaStream_t s2 = nullptr;
    static cudaEvent_t evStart = nullptr, evDinv = nullptr, evJoin = nullptr;
    static bool attrSet = false;
    if (!s2) {
        cudaStreamCreateWithFlags(&s2, cudaStreamNonBlocking);
        cudaEventCreateWithFlags(&evStart, cudaEventDisableTiming);
        cudaEventCreateWithFlags(&evDinv,  cudaEventDisableTiming);
        cudaEventCreateWithFlags(&evJoin,  cudaEventDisableTiming);
    }
    const int GSMEM   = 2 * 17408 * (int)sizeof(__half);           // 69632 B
    const int GSMEM40 = (17408 + 128 * 72) * (int)sizeof(__half);  // 53248 B
    if (!attrSet) {
        cudaFuncSetAttribute(k_gemm128h,
                             cudaFuncAttributeMaxDynamicSharedMemorySize, GSMEM);
        cudaFuncSetAttribute(k_gemm40h,
                             cudaFuncAttributeMaxDynamicSharedMemorySize, GSMEM40);
        attrSet = true;
    }

    const int tb = 256;
    int eblk = (E + tb - 1) / tb;
    int oblk = (n + 255) / 256;
    int gblk = (n + 127) / 128;
    int wblk = (int)(((long long)n * 32 + tb - 1) / tb);
    int x8   = (n * FEAT) / 8;
    int xblk = (x8 + tb - 1) / tb;

    // ---- fork s2 early: convX + convW are dependency-free ----
    cudaEventRecord(evStart, 0);
    cudaStreamWaitEvent(s2, evStart, 0);
    k_convX<<<xblk, tb, 0, s2>>>(x, x8);
    k_convW<<<(40960 + tb - 1) / tb, tb, 0, s2>>>(W0, W1, W2);

    // ---- main: degree -> offsets(dinv) ----
    k_count<<<eblk, tb>>>(ei, n, E);
    k_offset<<<oblk, 256>>>(n);
    cudaEventRecord(evDinv, 0);

    // ---- s2: layer-0 GEMM (needs convX/convW + dinv) || main: fill ----
    cudaStreamWaitEvent(s2, evDinv, 0);
    k_gemm128h<<<gblk, 256, GSMEM, s2>>>(pXh, pW0h, pHh, n);
    cudaEventRecord(evJoin, s2);

    k_fill<<<eblk, tb>>>(ei, n, E);
    cudaStreamWaitEvent(0, evJoin, 0);

    // ---- pipeline ----
    k_spmm128<<<wblk, tb>>>(pHh, pAGG, b0, n);
    k_gemm128h<<<gblk, 256, GSMEM>>>(pAGG, pW1h, pHh, n);
    k_spmm128<<<wblk, tb>>>(pHh, pAGG, b1, n);
    k_gemm40h<<<gblk, 256, GSMEM40>>>(pAGG, pH2h, n);
    k_spmm40h<<<wblk, tb>>>(pH2h, out, b2, n);
}

// round 15
// speedup vs baseline: 1.1130x; 1.0013x over previous
#include <cuda_runtime.h>
#include <cuda_fp16.h>

#define NN    100000
#define FEAT  128
#define CLS   40
#define EMAX  1600000

// ---- scratch (static device globals; no allocation allowed) ----
__device__ int    g_degi[NN];                // zero at load; re-zeroed by k_offset
__device__ float  g_dinv[NN];
__device__ __half g_Xh[(size_t)NN * FEAT];   // fp16 copy of input x
__device__ __half g_Hh[(size_t)NN * FEAT];   // pre-scaled fp16 messages h*dinv
__device__ __half g_AGG[(size_t)NN * FEAT];  // fp16 relu'd conv output
__device__ __half g_H2h[(size_t)NN * CLS];   // layer-2 pre-scaled fp16 messages
__device__ __half g_W0h[16384];
__device__ __half g_W1h[16384];
__device__ __half g_W2p[128 * 64];           // W2 padded 40->64 cols
__device__ int2   g_seg[NN];                 // x=segment start, y=cursor/end
__device__ int    g_csr[EMAX];
__device__ int    g_total;

// ---- helpers ----
__device__ __forceinline__ unsigned sm_u32(const void* p) {
    return (unsigned)__cvta_generic_to_shared(p);
}
__device__ __forceinline__ void ldm_x4(unsigned* r, unsigned a) {
    asm volatile("ldmatrix.sync.aligned.m8n8.x4.shared.b16 {%0,%1,%2,%3}, [%4];"
                 : "=r"(r[0]), "=r"(r[1]), "=r"(r[2]), "=r"(r[3]) : "r"(a));
}
__device__ __forceinline__ void ldm_x4t(unsigned* r, unsigned a) {
    asm volatile("ldmatrix.sync.aligned.m8n8.x4.trans.shared.b16 {%0,%1,%2,%3}, [%4];"
                 : "=r"(r[0]), "=r"(r[1]), "=r"(r[2]), "=r"(r[3]) : "r"(a));
}
__device__ __forceinline__ void mma16816(float* d, const unsigned* a,
                                         const unsigned* b) {
    asm volatile(
        "mma.sync.aligned.m16n8k16.row.col.f32.f16.f16.f32 "
        "{%0,%1,%2,%3},{%4,%5,%6,%7},{%8,%9},{%0,%1,%2,%3};"
        : "+f"(d[0]), "+f"(d[1]), "+f"(d[2]), "+f"(d[3])
        : "r"(a[0]), "r"(a[1]), "r"(a[2]), "r"(a[3]), "r"(b[0]), "r"(b[1]));
}
__device__ __forceinline__ void cp16(unsigned d, const void* s) {
    asm volatile("cp.async.ca.shared.global [%0], [%1], 16;" :: "r"(d), "l"(s));
}
__device__ __forceinline__ void cp16p(unsigned d, const void* s, bool p) {
    int sz = p ? 16 : 0;
    asm volatile("cp.async.ca.shared.global [%0], [%1], 16, %2;"
                 :: "r"(d), "l"(s), "r"(sz));
}
__device__ __forceinline__ void cp_commit() {
    asm volatile("cp.async.commit_group;" ::: "memory");
}
template <int N>
__device__ __forceinline__ void cp_waitg() {
    asm volatile("cp.async.wait_group %0;" :: "n"(N) : "memory");
}
__device__ __forceinline__ bool ei_is64(const void* ei, int n) {
    const unsigned long long* p = (const unsigned long long*)ei;
    return p[0] < (unsigned long long)n && p[1] < (unsigned long long)n;
}

// ------------------------------------------------------------------
// CSR build (unordered segments): count -> offset -> fill
// 2 edges per thread, vectorized edge reads
// ------------------------------------------------------------------
__global__ void k_count(const void* ei, int n, int E) {
    if (blockIdx.x == 0 && threadIdx.x == 0) g_total = 0;
    int e = (blockIdx.x * blockDim.x + threadIdx.x) * 2;
    if (e >= E) return;
    bool is64 = ei_is64(ei, n);
    if (e + 1 < E) {
        int d0, d1;
        if (is64) {
            longlong2 p = *(const longlong2*)((const long long*)ei + E + e);
            d0 = (int)p.x; d1 = (int)p.y;
        } else {
            int2 p = *(const int2*)((const int*)ei + E + e);
            d0 = p.x; d1 = p.y;
        }
        atomicAdd(&g_degi[d0], 1);
        atomicAdd(&g_degi[d1], 1);
    } else {
        int d = is64 ? (int)((const long long*)ei)[E + e]
                     : ((const int*)ei)[E + e];
        atomicAdd(&g_degi[d], 1);
    }
}

// per-256-node block: local scan + atomic base; writes dinv; zeroes degi
__global__ void k_offset(int n) {
    __shared__ int wsum[8];
    __shared__ int base;
    int t = threadIdx.x;
    int i = blockIdx.x * 256 + t;
    int lane = t & 31, warp = t >> 5;
    int deg = (i < n) ? g_degi[i] : 0;
    if (i < n) {
        g_dinv[i] = rsqrtf((float)deg + 1.f);
        g_degi[i] = 0;
    }
    int v = deg;
#pragma unroll
    for (int off = 1; off < 32; off <<= 1) {
        int x = __shfl_up_sync(0xffffffffu, v, off);
        if (lane >= off) v += x;
    }
    if (lane == 31) wsum[warp] = v;
    __syncthreads();
    if (warp == 0 && lane < 8) {
        int s = wsum[lane];
#pragma unroll
        for (int off = 1; off < 8; off <<= 1) {
            int x = __shfl_up_sync(0xffu, s, off);
            if (lane >= off) s += x;
        }
        wsum[lane] = s;
    }
    __syncthreads();
    if (t == 0) base = atomicAdd(&g_total, wsum[7]);
    __syncthreads();
    if (i < n) {
        int incl = v + (warp > 0 ? wsum[warp - 1] : 0);
        int r = base + incl - deg;
        g_seg[i] = make_int2(r, r);
    }
}

__global__ void k_fill(const void* ei, int n, int E) {
    int e = (blockIdx.x * blockDim.x + threadIdx.x) * 2;
    if (e >= E) return;
    bool is64 = ei_is64(ei, n);
    if (e + 1 < E) {
        int s0, s1, d0, d1;
        if (is64) {
            longlong2 ps = *(const longlong2*)((const long long*)ei + e);
            longlong2 pd = *(const longlong2*)((const long long*)ei + E + e);
            s0 = (int)ps.x; s1 = (int)ps.y; d0 = (int)pd.x; d1 = (int)pd.y;
        } else {
            int2 ps = *(const int2*)((const int*)ei + e);
            int2 pd = *(const int2*)((const int*)ei + E + e);
            s0 = ps.x; s1 = ps.y; d0 = pd.x; d1 = pd.y;
        }
        int p0 = atomicAdd(&g_seg[d0].y, 1);
        g_csr[p0] = s0;
        int p1 = atomicAdd(&g_seg[d1].y, 1);
        g_csr[p1] = s1;
    } else {
        int s, d;
        if (is64) {
            const long long* p = (const long long*)ei;
            s = (int)p[e]; d = (int)p[E + e];
        } else {
            const int* p = (const int*)ei;
            s = p[e]; d = p[E + e];
        }
        int pos = atomicAdd(&g_seg[d].y, 1);
        g_csr[pos] = s;
    }
}

// x -> fp16 (vectorized)
__global__ void k_convX(const float* __restrict__ x, int total8) {
    int i = blockIdx.x * blockDim.x + threadIdx.x;
    if (i >= total8) return;
    const float4* src = (const float4*)(x + (size_t)i * 8);
    float4 f0 = src[0], f1 = src[1];
    __half2 hh[4];
    hh[0] = __floats2half2_rn(f0.x, f0.y);
    hh[1] = __floats2half2_rn(f0.z, f0.w);
    hh[2] = __floats2half2_rn(f1.x, f1.y);
    hh[3] = __floats2half2_rn(f1.z, f1.w);
    *(uint4*)(g_Xh + (size_t)i * 8) = *(uint4*)hh;
}

// weights -> fp16 (W2 padded 40->64)
__global__ void k_convW(const float* W0, const float* W1, const float* W2) {
    int i = blockIdx.x * blockDim.x + threadIdx.x;
    if (i < 16384) {
        g_W0h[i] = __float2half_rn(W0[i]);
    } else if (i < 32768) {
        g_W1h[i - 16384] = __float2half_rn(W1[i - 16384]);
    } else if (i < 32768 + 128 * 64) {
        int j = i - 32768;
        int k = j >> 6, c = j & 63;
        g_W2p[j] = __float2half_rn(c < 40 ? W2[k * 40 + c] : 0.f);
    }
}

// ------------------------------------------------------------------
// Tensor-core GEMM (K=128, Nout=128), 2-stage cp.async pipeline, fp16 in:
//   h  = A @ Wh ; Hh = half(h * dinv)
// ------------------------------------------------------------------
#define SPITCH 136
#define AS(r, c) dsm[(r) * SPITCH + (c)]
#define WS(r, c) dsm[17408 + (r) * SPITCH + (c)]
#define HS(r, c) dsm[(r) * SPITCH + (c)]

__global__ __launch_bounds__(256)
void k_gemm128h(const __half* __restrict__ A, const __half* __restrict__ Wh,
                __half* __restrict__ Hh, int n) {
    extern __shared__ __half dsm[];
    const int tid  = threadIdx.x;
    const int lane = tid & 31;
    const int warp = tid >> 5;
    const int wm   = warp & 3;
    const int wn   = warp >> 2;
    const int row0 = blockIdx.x * 128;

    float acc[2][8][4];
#pragma unroll
    for (int mi = 0; mi < 2; mi++)
#pragma unroll
        for (int ni = 0; ni < 8; ni++)
#pragma unroll
            for (int q = 0; q < 4; q++) acc[mi][ni][q] = 0.f;

    {
        const int arow = tid >> 1;
        const int acol = (tid & 1) * 32;
        const int wrow = tid >> 2;
        const int wcol = (tid & 3) * 32;
        int gr = row0 + arow;
        bool ok = gr < n;
        const __half* Arow = A + (size_t)gr * 128;
#pragma unroll
        for (int s = 0; s < 2; s++) {
            int ak = s * 64 + acol;
#pragma unroll
            for (int u = 0; u < 4; u++)
                cp16p(sm_u32(&AS(arow, ak + u * 8)), Arow + ak + u * 8, ok);
            const __half* Wrow = Wh + (size_t)(s * 64 + wrow) * 128 + wcol;
#pragma unroll
            for (int u = 0; u < 4; u++)
                cp16(sm_u32(&WS(s * 64 + wrow, wcol + u * 8)), Wrow + u * 8);
            cp_commit();
        }
        cp_waitg<1>();
    }
    __syncthreads();

#pragma unroll
    for (int half = 0; half < 2; half++) {
        if (half == 1) {
            cp_waitg<0>();
            __syncthreads();
        }
#pragma unroll
        for (int kq = 0; kq < 4; kq++) {
            int kk = half * 4 + kq;
            unsigned af[2][4];
#pragma unroll
            for (int mi = 0; mi < 2; mi++) {
                int r = wm * 32 + mi * 16 + (lane & 15);
                int kh = kk * 16 + (lane >> 4) * 8;
                ldm_x4(af[mi], sm_u32(&AS(r, kh)));
            }
            unsigned bf[8][2];
#pragma unroll
            for (int nt = 0; nt < 4; nt++) {
                int g = lane >> 3, r = lane & 7;
                int krow = kk * 16 + (g & 1) * 8 + r;
                int ncol = wn * 64 + nt * 16 + (g >> 1) * 8;
                unsigned t[4];
                ldm_x4t(t, sm_u32(&WS(krow, ncol)));
                bf[nt * 2 + 0][0] = t[0]; bf[nt * 2 + 0][1] = t[1];
                bf[nt * 2 + 1][0] = t[2]; bf[nt * 2 + 1][1] = t[3];
            }
#pragma unroll
            for (int mi = 0; mi < 2; mi++)
#pragma unroll
                for (int ni = 0; ni < 8; ni++)
                    mma16816(acc[mi][ni], af[mi], bf[ni]);
        }
    }

    __syncthreads();
    {
        const int r1 = lane >> 2;
        const int c2 = (lane & 3) * 2;
#pragma unroll
        for (int mi = 0; mi < 2; mi++) {
            int r = wm * 32 + mi * 16 + r1;
#pragma unroll
            for (int ni = 0; ni < 8; ni++) {
                int col = wn * 64 + ni * 8 + c2;
                __half2 h01 = __floats2half2_rn(acc[mi][ni][0], acc[mi][ni][1]);
                __half2 h23 = __floats2half2_rn(acc[mi][ni][2], acc[mi][ni][3]);
                *(__half2*)&HS(r, col)     = h01;
                *(__half2*)&HS(r + 8, col) = h23;
            }
        }
    }
    __syncthreads();
    {
        int rrow  = tid >> 4;
        int chunk = tid & 15;
#pragma unroll
        for (int p = 0; p < 8; p++) {
            int r = p * 16 + rrow;
            int gr = row0 + r;
            if (gr < n) {
                __half2 d2 = __float2half2_rn(g_dinv[gr]);
                uint4 u = *(uint4*)&HS(r, chunk * 8);
                __half2* hp = (__half2*)&u;
                hp[0] = __hmul2(hp[0], d2); hp[1] = __hmul2(hp[1], d2);
                hp[2] = __hmul2(hp[2], d2); hp[3] = __hmul2(hp[3], d2);
                *(uint4*)(Hh + (size_t)gr * 128 + chunk * 8) = u;
            }
        }
    }
}

// ------------------------------------------------------------------
// Tensor-core GEMM (K=128, Nout=64 padded; 40 real), fp16 A + W, 2-stage:
//   h2 = A @ W2p ; H2h = half(h2 * dinv)
// ------------------------------------------------------------------
#define WS40(r, c) dsm[17408 + (r) * 72 + (c)]

__global__ __launch_bounds__(256)
void k_gemm40h(const __half* __restrict__ A, __half* __restrict__ H2h, int n) {
    extern __shared__ __half dsm[];
    const int tid  = threadIdx.x;
    const int lane = tid & 31;
    const int warp = tid >> 5;
    const int wm   = warp & 3;
    const int wn   = warp >> 2;
    const int row0 = blockIdx.x * 128;

    float acc[2][4][4];
#pragma unroll
    for (int mi = 0; mi < 2; mi++)
#pragma unroll
        for (int ni = 0; ni < 4; ni++)
#pragma unroll
            for (int q = 0; q < 4; q++) acc[mi][ni][q] = 0.f;

    {
        const int arow = tid >> 1;
        const int acol = (tid & 1) * 32;
        const int wrow = tid >> 2;
        const int wcol = (tid & 3) * 16;
        int gr = row0 + arow;
        bool ok = gr < n;
        const __half* Arow = A + (size_t)gr * 128;
#pragma unroll
        for (int s = 0; s < 2; s++) {
            int ak = s * 64 + acol;
#pragma unroll
            for (int u = 0; u < 4; u++)
                cp16p(sm_u32(&AS(arow, ak + u * 8)), Arow + ak + u * 8, ok);
            const __half* Wrow = g_W2p + (size_t)(s * 64 + wrow) * 64 + wcol;
#pragma unroll
            for (int u = 0; u < 2; u++)
                cp16(sm_u32(&WS40(s * 64 + wrow, wcol + u * 8)), Wrow + u * 8);
            cp_commit();
        }
        cp_waitg<1>();
    }
    __syncthreads();

#pragma unroll
    for (int half = 0; half < 2; half++) {
        if (half == 1) {
            cp_waitg<0>();
            __syncthreads();
        }
#pragma unroll
        for (int kq = 0; kq < 4; kq++) {
            int kk = half * 4 + kq;
            unsigned af[2][4];
#pragma unroll
            for (int mi = 0; mi < 2; mi++) {
                int r = wm * 32 + mi * 16 + (lane & 15);
                int kh = kk * 16 + (lane >> 4) * 8;
                ldm_x4(af[mi], sm_u32(&AS(r, kh)));
            }
            unsigned bf[4][2];
#pragma unroll
            for (int nt = 0; nt < 2; nt++) {
                int g = lane >> 3, r = lane & 7;
                int krow = kk * 16 + (g & 1) * 8 + r;
                int ncol = wn * 32 + nt * 16 + (g >> 1) * 8;
                unsigned t[4];
                ldm_x4t(t, sm_u32(&WS40(krow, ncol)));
                bf[nt * 2 + 0][0] = t[0]; bf[nt * 2 + 0][1] = t[1];
                bf[nt * 2 + 1][0] = t[2]; bf[nt * 2 + 1][1] = t[3];
            }
#pragma unroll
            for (int mi = 0; mi < 2; mi++)
#pragma unroll
                for (int ni = 0; ni < 4; ni++)
                    mma16816(acc[mi][ni], af[mi], bf[ni]);
        }
    }

    const int r1 = lane >> 2;
    const int c2 = (lane & 3) * 2;
#pragma unroll
    for (int mi = 0; mi < 2; mi++) {
        int gr0 = row0 + wm * 32 + mi * 16 + r1;
        int gr1 = gr0 + 8;
        float d0 = (gr0 < n) ? g_dinv[gr0] : 0.f;
        float d1 = (gr1 < n) ? g_dinv[gr1] : 0.f;
#pragma unroll
        for (int ni = 0; ni < 4; ni++) {
            int col = wn * 32 + ni * 8 + c2;
            if (col >= 40) continue;
            if (gr0 < n) {
                __half2 h = __floats2half2_rn(acc[mi][ni][0] * d0,
                                              acc[mi][ni][1] * d0);
                *(unsigned*)(H2h + (size_t)gr0 * 40 + col) = *(unsigned*)&h;
            }
            if (gr1 < n) {
                __half2 h = __floats2half2_rn(acc[mi][ni][2] * d1,
                                              acc[mi][ni][3] * d1);
                *(unsigned*)(H2h + (size_t)gr1 * 40 + col) = *(unsigned*)&h;
            }
        }
    }
}

// ------------------------------------------------------------------
// SpMM (fp16 messages; self-loop + bias + RELU folded), MLP=16:
//   AGG[d] = half(relu(dinv[d] * (Hh[d] + sum Hh[s]) + b))
// ------------------------------------------------------------------
__global__ __launch_bounds__(256)
void k_spmm128(const __half* __restrict__ hh, __half* __restrict__ agg,
               const float* __restrict__ b, int n) {
    int w = (blockIdx.x * blockDim.x + threadIdx.x) >> 5;
    if (w >= n) return;
    int lane = threadIdx.x & 31;
    int2 se = g_seg[w];
    float dd = g_dinv[w];
    uint2 us = *(const uint2*)(hh + (size_t)w * 128 + lane * 4);
    float2 s0 = __half22float2(*(const __half2*)&us.x);
    float2 s1 = __half22float2(*(const __half2*)&us.y);
    float4 acc = make_float4(s0.x, s0.y, s1.x, s1.y);

    int idx = se.x;
    int end = se.y;
    for (; idx + 16 <= end; idx += 16) {
        uint2 u[16];
#pragma unroll
        for (int q = 0; q < 16; q++) {
            int s = g_csr[idx + q];
            u[q] = *(const uint2*)(hh + (size_t)s * 128 + lane * 4);
        }
#pragma unroll
        for (int q = 0; q < 16; q++) {
            float2 f0 = __half22float2(*(const __half2*)&u[q].x);
            float2 f1 = __half22float2(*(const __half2*)&u[q].y);
            acc.x += f0.x; acc.y += f0.y; acc.z += f1.x; acc.w += f1.y;
        }
    }
    for (; idx + 4 <= end; idx += 4) {
        uint2 u[4];
#pragma unroll
        for (int q = 0; q < 4; q++) {
            int s = g_csr[idx + q];
            u[q] = *(const uint2*)(hh + (size_t)s * 128 + lane * 4);
        }
#pragma unroll
        for (int q = 0; q < 4; q++) {
            float2 f0 = __half22float2(*(const __half2*)&u[q].x);
            float2 f1 = __half22float2(*(const __half2*)&u[q].y);
            acc.x += f0.x; acc.y += f0.y; acc.z += f1.x; acc.w += f1.y;
        }
    }
    for (; idx < end; ++idx) {
        int s = g_csr[idx];
        uint2 u = *(const uint2*)(hh + (size_t)s * 128 + lane * 4);
        float2 f0 = __half22float2(*(const __half2*)&u.x);
        float2 f1 = __half22float2(*(const __half2*)&u.y);
        acc.x += f0.x; acc.y += f0.y; acc.z += f1.x; acc.w += f1.y;
    }
    float4 bv = *(const float4*)(b + lane * 4);
    float rx = fmaxf(dd * acc.x + bv.x, 0.f);
    float ry = fmaxf(dd * acc.y + bv.y, 0.f);
    float rz = fmaxf(dd * acc.z + bv.z, 0.f);
    float rw = fmaxf(dd * acc.w + bv.w, 0.f);
    __half2 r0 = __floats2half2_rn(rx, ry);
    __half2 r1 = __floats2half2_rn(rz, rw);
    uint2 res; res.x = *(unsigned*)&r0; res.y = *(unsigned*)&r1;
    *(uint2*)(agg + (size_t)w * 128 + lane * 4) = res;
}

// layer-2 final: OUT[d] = dinv[d] * (H2h[d] + sum H2h[s]) + b2 (fp32)
__global__ __launch_bounds__(256)
void k_spmm40h(const __half* __restrict__ hh, float* __restrict__ out,
               const float* __restrict__ b, int n) {
    int w = (blockIdx.x * blockDim.x + threadIdx.x) >> 5;
    if (w >= n) return;
    int lane = threadIdx.x & 31;
    if (lane >= 20) return;
    int2 se = g_seg[w];
    float dd = g_dinv[w];
    unsigned usf = *(const unsigned*)(hh + (size_t)w * 40 + lane * 2);
    float2 acc = __half22float2(*(const __half2*)&usf);

    int idx = se.x;
    int end = se.y;
    for (; idx + 8 <= end; idx += 8) {
        unsigned u[8];
#pragma unroll
        for (int q = 0; q < 8; q++) {
            int s = g_csr[idx + q];
            u[q] = *(const unsigned*)(hh + (size_t)s * 40 + lane * 2);
        }
#pragma unroll
        for (int q = 0; q < 8; q++) {
            float2 f = __half22float2(*(const __half2*)&u[q]);
            acc.x += f.x; acc.y += f.y;
        }
    }
    for (; idx < end; ++idx) {
        int s = g_csr[idx];
        unsigned u = *(const unsigned*)(hh + (size_t)s * 40 + lane * 2);
        float2 f = __half22float2(*(const __half2*)&u);
        acc.x += f.x; acc.y += f.y;
    }
    float2 bv = *(const float2*)(b + lane * 2);
    float2 res = make_float2(dd * acc.x + bv.x, dd * acc.y + bv.y);
    *(float2*)(out + (size_t)w * 40 + lane * 2) = res;
}

// ------------------------------------------------------------------
extern "C" void kernel_launch(void* const* d_in, const int* in_sizes, int n_in,
                              void* d_out, int out_size) {
    const float* x  = (const float*)d_in[0];
    const float* W0 = (const float*)d_in[1];
    const float* b0 = (const float*)d_in[2];
    const float* W1 = (const float*)d_in[3];
    const float* b1 = (const float*)d_in[4];
    const float* W2 = (const float*)d_in[5];
    const float* b2 = (const float*)d_in[6];
    const void*  ei = d_in[7];
    int n = in_sizes[0] / FEAT;
    int E = in_sizes[7] / 2;
    if (E > EMAX) E = EMAX;
    float* out = (float*)d_out;

    __half *pXh, *pHh, *pH2h, *pAGG, *pW0h, *pW1h;
    cudaGetSymbolAddress((void**)&pXh,  g_Xh);
    cudaGetSymbolAddress((void**)&pHh,  g_Hh);
    cudaGetSymbolAddress((void**)&pH2h, g_H2h);
    cudaGetSymbolAddress((void**)&pAGG, g_AGG);
    cudaGetSymbolAddress((void**)&pW0h, g_W0h);
    cudaGetSymbolAddress((void**)&pW1h, g_W1h);

    static cudaStream_t s2 = nullptr;
    static cudaEvent_t evStart = nullptr, evDinv = nullptr, evJoin = nullptr;
    static bool attrSet = false;
    if (!s2) {
        cudaStreamCreateWithFlags(&s2, cudaStreamNonBlocking);
        cudaEventCreateWithFlags(&evStart, cudaEventDisableTiming);
        cudaEventCreateWithFlags(&evDinv,  cudaEventDisableTiming);
        cudaEventCreateWithFlags(&evJoin,  cudaEventDisableTiming);
    }
    const int GSMEM   = 2 * 17408 * (int)sizeof(__half);           // 69632 B
    const int GSMEM40 = (17408 + 128 * 72) * (int)sizeof(__half);  // 53248 B
    if (!attrSet) {
        cudaFuncSetAttribute(k_gemm128h,
                             cudaFuncAttributeMaxDynamicSharedMemorySize, GSMEM);
        cudaFuncSetAttribute(k_gemm40h,
                             cudaFuncAttributeMaxDynamicSharedMemorySize, GSMEM40);
        attrSet = true;
    }

    const int tb = 256;
    int e2blk = ((E + 1) / 2 + tb - 1) / tb;
    int oblk  = (n + 255) / 256;
    int gblk  = (n + 127) / 128;
    int wblk  = (int)(((long long)n * 32 + tb - 1) / tb);
    int x8    = (n * FEAT) / 8;
    int xblk  = (x8 + tb - 1) / tb;

    // ---- fork s2 early: convX + convW are dependency-free ----
    cudaEventRecord(evStart, 0);
    cudaStreamWaitEvent(s2, evStart, 0);
    k_convX<<<xblk, tb, 0, s2>>>(x, x8);
    k_convW<<<(40960 + tb - 1) / tb, tb, 0, s2>>>(W0, W1, W2);

    // ---- main: degree -> offsets(dinv) ----
    k_count<<<e2blk, tb>>>(ei, n, E);
    k_offset<<<oblk, 256>>>(n);
    cudaEventRecord(evDinv, 0);

    // ---- s2: layer-0 GEMM (needs convX/convW + dinv) || main: fill ----
    cudaStreamWaitEvent(s2, evDinv, 0);
    k_gemm128h<<<gblk, 256, GSMEM, s2>>>(pXh, pW0h, pHh, n);
    cudaEventRecord(evJoin, s2);

    k_fill<<<e2blk, tb>>>(ei, n, E);
    cudaStreamWaitEvent(0, evJoin, 0);

    // ---- pipeline ----
    k_spmm128<<<wblk, tb>>>(pHh, pAGG, b0, n);
    k_gemm128h<<<gblk, 256, GSMEM>>>(pAGG, pW1h, pHh, n);
    k_spmm128<<<wblk, tb>>>(pHh, pAGG, b1, n);
    k_gemm40h<<<gblk, 256, GSMEM40>>>(pAGG, pH2h, n);
    k_spmm40h<<<wblk, tb>>>(pH2h, out, b2, n);
}